// round 6
// baseline (speedup 1.0000x reference)
#include <cuda_runtime.h>
#include <math.h>
#include <stdint.h>

#define DMODEL 1024
#define NHEAD  16
#define HDIM   64
#define DFF    2730
#define DHALT  256
#define BATCH  2
#define SEQ    2048
#define NROWS  (BATCH*SEQ)   // 4096

// ---------------- scratch (static device globals: allocation-guard safe) ---------
__device__ float g_h1[(size_t)NROWS*DMODEL];
__device__ float g_qkv[(size_t)NROWS*3*DMODEL];
__device__ float g_attn[(size_t)NROWS*DMODEL];
__device__ float g_x1[(size_t)NROWS*DMODEL];
__device__ float g_h2[(size_t)NROWS*DMODEL];
__device__ float g_u[(size_t)NROWS*DFF];
__device__ float g_v[(size_t)NROWS*DFF];
__device__ float g_hh[(size_t)NROWS*DHALT];

// ---------------- rmsnorm: one block per row --------------------------------
__global__ void rmsnorm_kernel(const float* __restrict__ x, const float* __restrict__ g,
                               float* __restrict__ y) {
    int row = blockIdx.x;
    const float* xr = x + (size_t)row * DMODEL;
    int t = threadIdx.x;
    float v[4];
    float ss = 0.f;
#pragma unroll
    for (int i = 0; i < 4; i++) { v[i] = xr[t + i * 256]; ss += v[i] * v[i]; }
    for (int off = 16; off; off >>= 1) ss += __shfl_xor_sync(0xffffffffu, ss, off);
    __shared__ float red[8];
    if ((t & 31) == 0) red[t >> 5] = ss;
    __syncthreads();
    if (t < 8) {
        float s2 = red[t];
        for (int off = 4; off; off >>= 1) s2 += __shfl_xor_sync(0xffu, s2, off);
        if (t == 0) red[0] = s2;
    }
    __syncthreads();
    float inv = rsqrtf(red[0] * (1.0f / DMODEL) + 1e-6f);
    float* yr = y + (size_t)row * DMODEL;
#pragma unroll
    for (int i = 0; i < 4; i++) {
        int c = t + i * 256;
        yr[c] = v[i] * inv * g[c];
    }
}

// ---------------- TF32 helpers ----------------------------------------------
__device__ __forceinline__ uint32_t f2tf32(float x) {
    uint32_t y;
    asm("cvt.rna.tf32.f32 %0, %1;" : "=r"(y) : "f"(x));
    return y;
}

__device__ __forceinline__ void mma_tf32(float c[4], const uint32_t a[4], const uint32_t b[2]) {
    asm volatile(
        "mma.sync.aligned.m16n8k8.row.col.f32.tf32.tf32.f32 "
        "{%0,%1,%2,%3}, {%4,%5,%6,%7}, {%8,%9}, {%0,%1,%2,%3};"
        : "+f"(c[0]), "+f"(c[1]), "+f"(c[2]), "+f"(c[3])
        : "r"(a[0]), "r"(a[1]), "r"(a[2]), "r"(a[3]), "r"(b[0]), "r"(b[1]));
}

// ---------------- TF32 tensor-core GEMM: C[M,N] = A[M,K] @ B[K,N] ------------
// MODE 0: plain   MODE 1: C = acc + E[m,n] (residual)   MODE 2: C = gelu(acc + E[n]) (bias)
// ASRC 0: A read directly   ASRC 1: A[m][k] = silu(A[m][k]) * A2[m][k]  (fused swiglu)
// Block 256 thr = 8 warps (2 x 4). BM=128 BN=128 BK=32, warp tile 64x32.
#define AS_STRIDE 36    // 32 + 4
#define BS_STRIDE 136   // 128 + 8
template <int MODE, int ASRC>
__global__ void __launch_bounds__(256) gemm_tc(const float* __restrict__ A,
                                               const float* __restrict__ A2,
                                               const float* __restrict__ Bm,
                                               float* __restrict__ C,
                                               const float* __restrict__ E,
                                               int M, int K, int N) {
    __shared__ float As[128 * AS_STRIDE];   // [m][k]
    __shared__ float Bs[32 * BS_STRIDE];    // [k][n]
    int tid = threadIdx.x;
    int w = tid >> 5, lane = tid & 31;
    int warpM = w >> 2, warpN = w & 3;          // 2 x 4
    int group = lane >> 2, tig = lane & 3;
    int m0 = blockIdx.y * 128, n0 = blockIdx.x * 128;

    float acc[4][4][4];
#pragma unroll
    for (int mi = 0; mi < 4; mi++)
#pragma unroll
        for (int ni = 0; ni < 4; ni++)
#pragma unroll
            for (int r = 0; r < 4; r++) acc[mi][ni][r] = 0.f;

    for (int k0 = 0; k0 < K; k0 += 32) {
        // A tile 128x32 (scalar coalesced; K may be ragged e.g. 2730)
#pragma unroll
        for (int i = 0; i < 16; i++) {
            int e = i * 256 + tid;
            int m = e >> 5, kk = e & 31;
            float val = 0.f;
            if (m0 + m < M && k0 + kk < K) {
                size_t idx = (size_t)(m0 + m) * K + k0 + kk;
                val = A[idx];
                if (ASRC == 1) {
                    float s = val / (1.f + expf(-val));   // silu(u)
                    val = s * A2[idx];                    // * v
                }
            }
            As[m * AS_STRIDE + kk] = __uint_as_float(f2tf32(val));
        }
        // B tile 32x128
#pragma unroll
        for (int i = 0; i < 16; i++) {
            int e = i * 256 + tid;
            int kk = e >> 7, n = e & 127;
            float val = 0.f;
            if (k0 + kk < K && n0 + n < N) val = Bm[(size_t)(k0 + kk) * N + n0 + n];
            Bs[kk * BS_STRIDE + n] = __uint_as_float(f2tf32(val));
        }
        __syncthreads();

#pragma unroll
        for (int ks = 0; ks < 32; ks += 8) {
            uint32_t afrag[4][4], bfrag[4][2];
#pragma unroll
            for (int mi = 0; mi < 4; mi++) {
                int rm = warpM * 64 + mi * 16;
                afrag[mi][0] = __float_as_uint(As[(rm + group)     * AS_STRIDE + ks + tig]);
                afrag[mi][1] = __float_as_uint(As[(rm + group + 8) * AS_STRIDE + ks + tig]);
                afrag[mi][2] = __float_as_uint(As[(rm + group)     * AS_STRIDE + ks + tig + 4]);
                afrag[mi][3] = __float_as_uint(As[(rm + group + 8) * AS_STRIDE + ks + tig + 4]);
            }
#pragma unroll
            for (int ni = 0; ni < 4; ni++) {
                int cn = warpN * 32 + ni * 8;
                bfrag[ni][0] = __float_as_uint(Bs[(ks + tig)     * BS_STRIDE + cn + group]);
                bfrag[ni][1] = __float_as_uint(Bs[(ks + tig + 4) * BS_STRIDE + cn + group]);
            }
#pragma unroll
            for (int mi = 0; mi < 4; mi++)
#pragma unroll
                for (int ni = 0; ni < 4; ni++)
                    mma_tf32(acc[mi][ni], afrag[mi], bfrag[ni]);
        }
        __syncthreads();
    }

    // epilogue: c0:(r,c) c1:(r,c+1) c2:(r+8,c) c3:(r+8,c+1), r=base+group, c=base+tig*2
#pragma unroll
    for (int mi = 0; mi < 4; mi++) {
#pragma unroll
        for (int ni = 0; ni < 4; ni++) {
#pragma unroll
            for (int r = 0; r < 4; r++) {
                int row = m0 + warpM * 64 + mi * 16 + group + (r >> 1) * 8;
                int col = n0 + warpN * 32 + ni * 8 + tig * 2 + (r & 1);
                if (row >= M || col >= N) continue;
                float val = acc[mi][ni][r];
                if (MODE == 1) val += E[(size_t)row * N + col];
                if (MODE == 2) {
                    val += E[col];
                    val = 0.5f * val * (1.f + erff(val * 0.70710678118654752f));
                }
                C[(size_t)row * N + col] = val;
            }
        }
    }
}

// ---------------- flash attention: BQ=BK=64, HD=64, online softmax -----------
__global__ void attn_kernel(const float* __restrict__ qkv, float* __restrict__ out) {
    extern __shared__ float sm[];
    float* Qs = sm;               // 64*65
    float* Ks = Qs + 64 * 65;
    float* Vs = Ks + 64 * 65;
    float* Ss = Vs + 64 * 65;
    int tid = threadIdx.x;
    int tx = tid & 15, ty = tid >> 4;
    int bh = blockIdx.y;
    int b = bh >> 4, h = bh & 15;
    int qt0 = blockIdx.x * 64;
    size_t base = (size_t)b * SEQ * 3072;

#pragma unroll
    for (int i = 0; i < 4; i++) {
        int e = i * 256 + tid;
        int r = e >> 4, dq = e & 15;
        float4 v = *(const float4*)&qkv[base + (size_t)(qt0 + r) * 3072 + h * 64 + dq * 4];
        float* d = &Qs[r * 65 + dq * 4];
        d[0] = v.x; d[1] = v.y; d[2] = v.z; d[3] = v.w;
    }

    float m_i[4], l_i[4], acc[4][4];
#pragma unroll
    for (int i = 0; i < 4; i++) {
        m_i[i] = -1e30f; l_i[i] = 0.f;
#pragma unroll
        for (int j = 0; j < 4; j++) acc[i][j] = 0.f;
    }

    int jt_max = blockIdx.x;
    for (int jt = 0; jt <= jt_max; jt++) {
        int j0 = jt * 64;
        __syncthreads();
#pragma unroll
        for (int i = 0; i < 4; i++) {
            int e = i * 256 + tid;
            int r = e >> 4, dq = e & 15;
            float4 kv = *(const float4*)&qkv[base + (size_t)(j0 + r) * 3072 + 1024 + h * 64 + dq * 4];
            float* dk = &Ks[r * 65 + dq * 4];
            dk[0] = kv.x; dk[1] = kv.y; dk[2] = kv.z; dk[3] = kv.w;
            float4 vv = *(const float4*)&qkv[base + (size_t)(j0 + r) * 3072 + 2048 + h * 64 + dq * 4];
            float* dv = &Vs[r * 65 + dq * 4];
            dv[0] = vv.x; dv[1] = vv.y; dv[2] = vv.z; dv[3] = vv.w;
        }
        __syncthreads();

        float s[4][4];
#pragma unroll
        for (int i = 0; i < 4; i++)
#pragma unroll
            for (int j = 0; j < 4; j++) s[i][j] = 0.f;
#pragma unroll
        for (int d = 0; d < 64; d++) {
            float a[4], bq[4];
#pragma unroll
            for (int i = 0; i < 4; i++) a[i] = Qs[(ty * 4 + i) * 65 + d];
#pragma unroll
            for (int j = 0; j < 4; j++) bq[j] = Ks[(tx * 4 + j) * 65 + d];
#pragma unroll
            for (int i = 0; i < 4; i++)
#pragma unroll
                for (int j = 0; j < 4; j++) s[i][j] = fmaf(a[i], bq[j], s[i][j]);
        }
        bool diag = (jt == jt_max);
#pragma unroll
        for (int i = 0; i < 4; i++)
#pragma unroll
            for (int j = 0; j < 4; j++) {
                s[i][j] *= 0.125f;
                if (diag && (j0 + tx * 4 + j > qt0 + ty * 4 + i)) s[i][j] = -1e30f;
            }

#pragma unroll
        for (int i = 0; i < 4; i++) {
            float tm = fmaxf(fmaxf(s[i][0], s[i][1]), fmaxf(s[i][2], s[i][3]));
            for (int off = 8; off; off >>= 1) tm = fmaxf(tm, __shfl_xor_sync(0xffffffffu, tm, off, 16));
            float nm = fmaxf(m_i[i], tm);
            float rs = 0.f;
#pragma unroll
            for (int j = 0; j < 4; j++) { s[i][j] = expf(s[i][j] - nm); rs += s[i][j]; }
            for (int off = 8; off; off >>= 1) rs += __shfl_xor_sync(0xffffffffu, rs, off, 16);
            float f = expf(m_i[i] - nm);
            l_i[i] = l_i[i] * f + rs;
            m_i[i] = nm;
#pragma unroll
            for (int j = 0; j < 4; j++) acc[i][j] *= f;
        }
#pragma unroll
        for (int i = 0; i < 4; i++)
#pragma unroll
            for (int j = 0; j < 4; j++) Ss[(ty * 4 + i) * 65 + tx * 4 + j] = s[i][j];
        __syncthreads();
#pragma unroll
        for (int jj = 0; jj < 64; jj++) {
            float p[4], vv[4];
#pragma unroll
            for (int i = 0; i < 4; i++) p[i] = Ss[(ty * 4 + i) * 65 + jj];
#pragma unroll
            for (int j = 0; j < 4; j++) vv[j] = Vs[jj * 65 + tx * 4 + j];
#pragma unroll
            for (int i = 0; i < 4; i++)
#pragma unroll
                for (int j = 0; j < 4; j++) acc[i][j] = fmaf(p[i], vv[j], acc[i][j]);
        }
    }
#pragma unroll
    for (int i = 0; i < 4; i++) {
        float inv = 1.f / l_i[i];
        int r = qt0 + ty * 4 + i;
#pragma unroll
        for (int j = 0; j < 4; j++)
            out[(size_t)(b * SEQ + r) * DMODEL + h * 64 + tx * 4 + j] = acc[i][j] * inv;
    }
}

// ---------------- halt head --------------------------------------------------
__global__ void halt_kernel(const float* __restrict__ hh, const float* __restrict__ Wh2,
                            const float* __restrict__ bh2, const float* __restrict__ cum,
                            float* __restrict__ halt_out, float* __restrict__ cum_out) {
    int row = blockIdx.x;
    int t = threadIdx.x;
    float p = hh[(size_t)row * DHALT + t] * Wh2[t];
    for (int off = 16; off; off >>= 1) p += __shfl_xor_sync(0xffffffffu, p, off);
    __shared__ float red[8];
    if ((t & 31) == 0) red[t >> 5] = p;
    __syncthreads();
    if (t == 0) {
        float sum = red[0] + red[1] + red[2] + red[3] + red[4] + red[5] + red[6] + red[7] + bh2[0];
        float hp = 1.f / (1.f + expf(-sum));
        float c = cum[row];
        float still = (c < 0.99f) ? 1.f : 0.f;
        halt_out[row] = hp;
        cum_out[row] = c + hp * still;
    }
}

// ---------------- launch ------------------------------------------------------
extern "C" void kernel_launch(void* const* d_in, const int* in_sizes, int n_in,
                              void* d_out, int out_size) {
    const float* x    = (const float*)d_in[0];
    const float* cum  = (const float*)d_in[1];
    const float* g1   = (const float*)d_in[2];
    const float* g2   = (const float*)d_in[3];
    const float* Wqkv = (const float*)d_in[4];
    const float* Wo   = (const float*)d_in[5];
    const float* W1   = (const float*)d_in[6];
    const float* W2   = (const float*)d_in[7];
    const float* W3   = (const float*)d_in[8];
    const float* Wh1  = (const float*)d_in[9];
    const float* bh1  = (const float*)d_in[10];
    const float* Wh2  = (const float*)d_in[11];
    const float* bh2  = (const float*)d_in[12];

    float* outx = (float*)d_out;
    float* outh = outx + (size_t)NROWS * DMODEL;
    float* outc = outh + NROWS;

    float *h1, *qkvb, *attnb, *x1, *h2, *u, *v, *hhp;
    cudaGetSymbolAddress((void**)&h1,   g_h1);
    cudaGetSymbolAddress((void**)&qkvb, g_qkv);
    cudaGetSymbolAddress((void**)&attnb,g_attn);
    cudaGetSymbolAddress((void**)&x1,   g_x1);
    cudaGetSymbolAddress((void**)&h2,   g_h2);
    cudaGetSymbolAddress((void**)&u,    g_u);
    cudaGetSymbolAddress((void**)&v,    g_v);
    cudaGetSymbolAddress((void**)&hhp,  g_hh);

    const int attn_smem = 4 * 64 * 65 * sizeof(float);  // 66560 B
    cudaFuncSetAttribute(attn_kernel, cudaFuncAttributeMaxDynamicSharedMemorySize, attn_smem);

    // 1. h1 = rmsnorm(x, g1)
    rmsnorm_kernel<<<NROWS, 256>>>(x, g1, h1);
    // 2. qkv = h1 @ Wqkv   (M=4096 K=1024 N=3072)
    gemm_tc<0,0><<<dim3((3 * DMODEL + 127) / 128, NROWS / 128), 256>>>(
        h1, nullptr, Wqkv, qkvb, nullptr, NROWS, DMODEL, 3 * DMODEL);
    // 3. attention
    attn_kernel<<<dim3(SEQ / 64, BATCH * NHEAD), 256, attn_smem>>>(qkvb, attnb);
    // 4. x1 = x + attn @ Wo
    gemm_tc<1,0><<<dim3((DMODEL + 127) / 128, NROWS / 128), 256>>>(
        attnb, nullptr, Wo, x1, x, NROWS, DMODEL, DMODEL);
    // 5. h2 = rmsnorm(x1, g2)
    rmsnorm_kernel<<<NROWS, 256>>>(x1, g2, h2);
    // 6. u = h2 @ W1, v = h2 @ W2   (N=2730)
    gemm_tc<0,0><<<dim3((DFF + 127) / 128, NROWS / 128), 256>>>(
        h2, nullptr, W1, u, nullptr, NROWS, DMODEL, DFF);
    gemm_tc<0,0><<<dim3((DFF + 127) / 128, NROWS / 128), 256>>>(
        h2, nullptr, W2, v, nullptr, NROWS, DMODEL, DFF);
    // 7+8. final x = x1 + (silu(u)*v) @ W3 -> straight into d_out  (K=2730, fused swiglu)
    gemm_tc<1,1><<<dim3((DMODEL + 127) / 128, NROWS / 128), 256>>>(
        u, v, W3, outx, x1, NROWS, DFF, DMODEL);
    // 9. hh = gelu(x @ Wh1 + bh1)   (N=256)
    gemm_tc<2,0><<<dim3((DHALT + 127) / 128, NROWS / 128), 256>>>(
        outx, nullptr, Wh1, hhp, bh1, NROWS, DMODEL, DHALT);
    // 10. halt probs + cum update
    halt_kernel<<<NROWS, 256>>>(hhp, Wh2, bh2, cum, outh, outc);
}

// round 7
// speedup vs baseline: 2.5480x; 2.5480x over previous
#include <cuda_runtime.h>
#include <math.h>
#include <stdint.h>

#define DMODEL 1024
#define NHEAD  16
#define HDIM   64
#define DFF    2730
#define DHALT  256
#define BATCH  2
#define SEQ    2048
#define NROWS  (BATCH*SEQ)   // 4096

// ---------------- scratch (static device globals: allocation-guard safe) ---------
__device__ float g_h1[(size_t)NROWS*DMODEL];
__device__ float g_qkv[(size_t)NROWS*3*DMODEL];
__device__ float g_attn[(size_t)NROWS*DMODEL];
__device__ float g_x1[(size_t)NROWS*DMODEL];
__device__ float g_h2[(size_t)NROWS*DMODEL];
__device__ float g_u[(size_t)NROWS*DFF];
__device__ float g_v[(size_t)NROWS*DFF];
__device__ float g_hh[(size_t)NROWS*DHALT];

// ---------------- rmsnorm: one block per row --------------------------------
__global__ void rmsnorm_kernel(const float* __restrict__ x, const float* __restrict__ g,
                               float* __restrict__ y) {
    int row = blockIdx.x;
    const float* xr = x + (size_t)row * DMODEL;
    int t = threadIdx.x;
    float v[4];
    float ss = 0.f;
#pragma unroll
    for (int i = 0; i < 4; i++) { v[i] = xr[t + i * 256]; ss += v[i] * v[i]; }
    for (int off = 16; off; off >>= 1) ss += __shfl_xor_sync(0xffffffffu, ss, off);
    __shared__ float red[8];
    if ((t & 31) == 0) red[t >> 5] = ss;
    __syncthreads();
    if (t < 8) {
        float s2 = red[t];
        for (int off = 4; off; off >>= 1) s2 += __shfl_xor_sync(0xffu, s2, off);
        if (t == 0) red[0] = s2;
    }
    __syncthreads();
    float inv = rsqrtf(red[0] * (1.0f / DMODEL) + 1e-6f);
    float* yr = y + (size_t)row * DMODEL;
#pragma unroll
    for (int i = 0; i < 4; i++) {
        int c = t + i * 256;
        yr[c] = v[i] * inv * g[c];
    }
}

// ---------------- async-copy + mma helpers -----------------------------------
__device__ __forceinline__ uint32_t s2u(const void* p) {
    return (uint32_t)__cvta_generic_to_shared(p);
}
__device__ __forceinline__ void cp16(uint32_t d, const void* s) {
    asm volatile("cp.async.cg.shared.global [%0], [%1], 16;" :: "r"(d), "l"(s));
}
__device__ __forceinline__ void cp4(uint32_t d, const void* s) {
    asm volatile("cp.async.ca.shared.global [%0], [%1], 4;" :: "r"(d), "l"(s));
}
__device__ __forceinline__ void cp_commit() {
    asm volatile("cp.async.commit_group;");
}
__device__ __forceinline__ void mma_tf32(float c[4], const uint32_t a[4], const uint32_t b[2]) {
    asm volatile(
        "mma.sync.aligned.m16n8k8.row.col.f32.tf32.tf32.f32 "
        "{%0,%1,%2,%3}, {%4,%5,%6,%7}, {%8,%9}, {%0,%1,%2,%3};"
        : "+f"(c[0]), "+f"(c[1]), "+f"(c[2]), "+f"(c[3])
        : "r"(a[0]), "r"(a[1]), "r"(a[2]), "r"(a[3]), "r"(b[0]), "r"(b[1]));
}

// ---------------- TF32 tensor-core GEMM v2 -----------------------------------
// C[M,N] = A[M,K] @ B[K,N]
// MODE 0: plain  MODE 1: C = acc + E[m,n]  MODE 2: C = gelu(acc + E[n])
// AVEC 1: 16B cp.async for A (requires K%4==0)   AVEC 0: 4B cp.async + k guard
// BVEC 1: 16B cp.async for B (requires N%128==0) BVEC 0: 4B cp.async + n,k guards
// Requires M % 128 == 0 (grid-exact; epilogue still guards).
// Block 256 thr = 8 warps (2x4). BM=128 BN=128 BK=32, warp tile 64x32, 2-stage.
#define AS_STRIDE 36    // 32 + 4 : frag addr 4g+t mod 32 distinct -> conflict-free
#define BS_STRIDE 136   // 128 + 8: frag addr 8t+g mod 32 distinct -> conflict-free
#define A_TILE (128 * AS_STRIDE)   // 4608 floats
#define B_TILE (32 * BS_STRIDE)    // 4352 floats
#define STAGE  (A_TILE + B_TILE)   // 8960 floats; 2 stages = 71680 B

template <int MODE, int AVEC, int BVEC>
__global__ void __launch_bounds__(256) gemm_tc(const float* __restrict__ A,
                                               const float* __restrict__ Bm,
                                               float* __restrict__ C,
                                               const float* __restrict__ E,
                                               int M, int K, int N) {
    extern __shared__ float smem[];
    int tid = threadIdx.x;
    int w = tid >> 5, lane = tid & 31;
    int warpM = w >> 2, warpN = w & 3;          // 2 x 4
    int group = lane >> 2, tig = lane & 3;
    int m0 = blockIdx.y * 128, n0 = blockIdx.x * 128;

    // ---- tile loaders (cp.async into stage buffer) ----
    auto load_tile = [&](int k0, int stg) {
        float* sA = smem + stg * STAGE;
        float* sB = sA + A_TILE;
        if (AVEC) {
#pragma unroll
            for (int i = 0; i < 4; i++) {        // A: 128x32, 4 float4 per thread
                int c = i * 256 + tid;
                int m = c >> 3, k4 = (c & 7) * 4;
                float* dp = sA + m * AS_STRIDE + k4;
                const float* sp = A + (size_t)(m0 + m) * K + k0 + k4;
                if (k0 + k4 + 4 <= K) cp16(s2u(dp), sp);
                else {
#pragma unroll
                    for (int e = 0; e < 4; e++) dp[e] = (k0 + k4 + e < K) ? sp[e] : 0.f;
                }
            }
        } else {
#pragma unroll
            for (int i = 0; i < 16; i++) {       // A: 4B path (ragged K)
                int c = i * 256 + tid;
                int m = c >> 5, kk = c & 31;
                float* dp = sA + m * AS_STRIDE + kk;
                if (k0 + kk < K) cp4(s2u(dp), A + (size_t)(m0 + m) * K + k0 + kk);
                else *dp = 0.f;
            }
        }
        if (BVEC) {
#pragma unroll
            for (int i = 0; i < 4; i++) {        // B: 32x128, 4 float4 per thread
                int c = i * 256 + tid;
                int kk = c >> 5, n4 = (c & 31) * 4;
                float* dp = sB + kk * BS_STRIDE + n4;
                if (k0 + kk < K) cp16(s2u(dp), Bm + (size_t)(k0 + kk) * N + n0 + n4);
                else { dp[0] = 0.f; dp[1] = 0.f; dp[2] = 0.f; dp[3] = 0.f; }
            }
        } else {
#pragma unroll
            for (int i = 0; i < 16; i++) {       // B: 4B path (ragged N)
                int c = i * 256 + tid;
                int kk = c >> 7, n = c & 127;
                float* dp = sB + kk * BS_STRIDE + n;
                if (k0 + kk < K && n0 + n < N) cp4(s2u(dp), Bm + (size_t)(k0 + kk) * N + n0 + n);
                else *dp = 0.f;
            }
        }
    };

    float acc[4][4][4];
#pragma unroll
    for (int mi = 0; mi < 4; mi++)
#pragma unroll
        for (int ni = 0; ni < 4; ni++)
#pragma unroll
            for (int r = 0; r < 4; r++) acc[mi][ni][r] = 0.f;

    int ntiles = (K + 31) / 32;
    load_tile(0, 0);
    cp_commit();

    for (int t = 0; t < ntiles; t++) {
        if (t + 1 < ntiles) {
            load_tile((t + 1) * 32, (t + 1) & 1);
            cp_commit();
            asm volatile("cp.async.wait_group 1;");
        } else {
            asm volatile("cp.async.wait_group 0;");
        }
        __syncthreads();

        const float* sA = smem + (t & 1) * STAGE;
        const float* sB = sA + A_TILE;
#pragma unroll
        for (int ks = 0; ks < 32; ks += 8) {
            uint32_t afrag[4][4], bfrag[4][2];
#pragma unroll
            for (int mi = 0; mi < 4; mi++) {
                int rm = warpM * 64 + mi * 16;
                afrag[mi][0] = __float_as_uint(sA[(rm + group)     * AS_STRIDE + ks + tig]);
                afrag[mi][1] = __float_as_uint(sA[(rm + group + 8) * AS_STRIDE + ks + tig]);
                afrag[mi][2] = __float_as_uint(sA[(rm + group)     * AS_STRIDE + ks + tig + 4]);
                afrag[mi][3] = __float_as_uint(sA[(rm + group + 8) * AS_STRIDE + ks + tig + 4]);
            }
#pragma unroll
            for (int ni = 0; ni < 4; ni++) {
                int cn = warpN * 32 + ni * 8;
                bfrag[ni][0] = __float_as_uint(sB[(ks + tig)     * BS_STRIDE + cn + group]);
                bfrag[ni][1] = __float_as_uint(sB[(ks + tig + 4) * BS_STRIDE + cn + group]);
            }
#pragma unroll
            for (int mi = 0; mi < 4; mi++)
#pragma unroll
                for (int ni = 0; ni < 4; ni++)
                    mma_tf32(acc[mi][ni], afrag[mi], bfrag[ni]);
        }
        __syncthreads();
    }

    // epilogue: c0:(r,c) c1:(r,c+1) c2:(r+8,c) c3:(r+8,c+1)
#pragma unroll
    for (int mi = 0; mi < 4; mi++) {
#pragma unroll
        for (int ni = 0; ni < 4; ni++) {
#pragma unroll
            for (int r = 0; r < 4; r++) {
                int row = m0 + warpM * 64 + mi * 16 + group + (r >> 1) * 8;
                int col = n0 + warpN * 32 + ni * 8 + tig * 2 + (r & 1);
                if (row >= M || col >= N) continue;
                float val = acc[mi][ni][r];
                if (MODE == 1) val += E[(size_t)row * N + col];
                if (MODE == 2) {
                    val += E[col];
                    val = 0.5f * val * (1.f + erff(val * 0.70710678118654752f));
                }
                C[(size_t)row * N + col] = val;
            }
        }
    }
}

// ---------------- flash attention: BQ=BK=64, HD=64, online softmax -----------
__global__ void attn_kernel(const float* __restrict__ qkv, float* __restrict__ out) {
    extern __shared__ float sm[];
    float* Qs = sm;               // 64*65
    float* Ks = Qs + 64 * 65;
    float* Vs = Ks + 64 * 65;
    float* Ss = Vs + 64 * 65;
    int tid = threadIdx.x;
    int tx = tid & 15, ty = tid >> 4;
    int bh = blockIdx.y;
    int b = bh >> 4, h = bh & 15;
    int qt0 = blockIdx.x * 64;
    size_t base = (size_t)b * SEQ * 3072;

#pragma unroll
    for (int i = 0; i < 4; i++) {
        int e = i * 256 + tid;
        int r = e >> 4, dq = e & 15;
        float4 v = *(const float4*)&qkv[base + (size_t)(qt0 + r) * 3072 + h * 64 + dq * 4];
        float* d = &Qs[r * 65 + dq * 4];
        d[0] = v.x; d[1] = v.y; d[2] = v.z; d[3] = v.w;
    }

    float m_i[4], l_i[4], acc[4][4];
#pragma unroll
    for (int i = 0; i < 4; i++) {
        m_i[i] = -1e30f; l_i[i] = 0.f;
#pragma unroll
        for (int j = 0; j < 4; j++) acc[i][j] = 0.f;
    }

    int jt_max = blockIdx.x;
    for (int jt = 0; jt <= jt_max; jt++) {
        int j0 = jt * 64;
        __syncthreads();
#pragma unroll
        for (int i = 0; i < 4; i++) {
            int e = i * 256 + tid;
            int r = e >> 4, dq = e & 15;
            float4 kv = *(const float4*)&qkv[base + (size_t)(j0 + r) * 3072 + 1024 + h * 64 + dq * 4];
            float* dk = &Ks[r * 65 + dq * 4];
            dk[0] = kv.x; dk[1] = kv.y; dk[2] = kv.z; dk[3] = kv.w;
            float4 vv = *(const float4*)&qkv[base + (size_t)(j0 + r) * 3072 + 2048 + h * 64 + dq * 4];
            float* dv = &Vs[r * 65 + dq * 4];
            dv[0] = vv.x; dv[1] = vv.y; dv[2] = vv.z; dv[3] = vv.w;
        }
        __syncthreads();

        float s[4][4];
#pragma unroll
        for (int i = 0; i < 4; i++)
#pragma unroll
            for (int j = 0; j < 4; j++) s[i][j] = 0.f;
#pragma unroll
        for (int d = 0; d < 64; d++) {
            float a[4], bq[4];
#pragma unroll
            for (int i = 0; i < 4; i++) a[i] = Qs[(ty * 4 + i) * 65 + d];
#pragma unroll
            for (int j = 0; j < 4; j++) bq[j] = Ks[(tx * 4 + j) * 65 + d];
#pragma unroll
            for (int i = 0; i < 4; i++)
#pragma unroll
                for (int j = 0; j < 4; j++) s[i][j] = fmaf(a[i], bq[j], s[i][j]);
        }
        bool diag = (jt == jt_max);
#pragma unroll
        for (int i = 0; i < 4; i++)
#pragma unroll
            for (int j = 0; j < 4; j++) {
                s[i][j] *= 0.125f;
                if (diag && (j0 + tx * 4 + j > qt0 + ty * 4 + i)) s[i][j] = -1e30f;
            }

#pragma unroll
        for (int i = 0; i < 4; i++) {
            float tm = fmaxf(fmaxf(s[i][0], s[i][1]), fmaxf(s[i][2], s[i][3]));
            for (int off = 8; off; off >>= 1) tm = fmaxf(tm, __shfl_xor_sync(0xffffffffu, tm, off, 16));
            float nm = fmaxf(m_i[i], tm);
            float rs = 0.f;
#pragma unroll
            for (int j = 0; j < 4; j++) { s[i][j] = expf(s[i][j] - nm); rs += s[i][j]; }
            for (int off = 8; off; off >>= 1) rs += __shfl_xor_sync(0xffffffffu, rs, off, 16);
            float f = expf(m_i[i] - nm);
            l_i[i] = l_i[i] * f + rs;
            m_i[i] = nm;
#pragma unroll
            for (int j = 0; j < 4; j++) acc[i][j] *= f;
        }
#pragma unroll
        for (int i = 0; i < 4; i++)
#pragma unroll
            for (int j = 0; j < 4; j++) Ss[(ty * 4 + i) * 65 + tx * 4 + j] = s[i][j];
        __syncthreads();
#pragma unroll
        for (int jj = 0; jj < 64; jj++) {
            float p[4], vv[4];
#pragma unroll
            for (int i = 0; i < 4; i++) p[i] = Ss[(ty * 4 + i) * 65 + jj];
#pragma unroll
            for (int j = 0; j < 4; j++) vv[j] = Vs[jj * 65 + tx * 4 + j];
#pragma unroll
            for (int i = 0; i < 4; i++)
#pragma unroll
                for (int j = 0; j < 4; j++) acc[i][j] = fmaf(p[i], vv[j], acc[i][j]);
        }
    }
#pragma unroll
    for (int i = 0; i < 4; i++) {
        float inv = 1.f / l_i[i];
        int r = qt0 + ty * 4 + i;
#pragma unroll
        for (int j = 0; j < 4; j++)
            out[(size_t)(b * SEQ + r) * DMODEL + h * 64 + tx * 4 + j] = acc[i][j] * inv;
    }
}

// ---------------- swiglu elementwise (float4): u = silu(u) * v ---------------
__global__ void swiglu_kernel(float4* __restrict__ u, const float4* __restrict__ v, int n4) {
    int i = blockIdx.x * blockDim.x + threadIdx.x;
    if (i < n4) {
        float4 a = u[i], b = v[i];
        a.x = a.x / (1.f + expf(-a.x)) * b.x;
        a.y = a.y / (1.f + expf(-a.y)) * b.y;
        a.z = a.z / (1.f + expf(-a.z)) * b.z;
        a.w = a.w / (1.f + expf(-a.w)) * b.w;
        u[i] = a;
    }
}

// ---------------- halt head --------------------------------------------------
__global__ void halt_kernel(const float* __restrict__ hh, const float* __restrict__ Wh2,
                            const float* __restrict__ bh2, const float* __restrict__ cum,
                            float* __restrict__ halt_out, float* __restrict__ cum_out) {
    int row = blockIdx.x;
    int t = threadIdx.x;
    float p = hh[(size_t)row * DHALT + t] * Wh2[t];
    for (int off = 16; off; off >>= 1) p += __shfl_xor_sync(0xffffffffu, p, off);
    __shared__ float red[8];
    if ((t & 31) == 0) red[t >> 5] = p;
    __syncthreads();
    if (t == 0) {
        float sum = red[0] + red[1] + red[2] + red[3] + red[4] + red[5] + red[6] + red[7] + bh2[0];
        float hp = 1.f / (1.f + expf(-sum));
        float c = cum[row];
        float still = (c < 0.99f) ? 1.f : 0.f;
        halt_out[row] = hp;
        cum_out[row] = c + hp * still;
    }
}

// ---------------- launch ------------------------------------------------------
extern "C" void kernel_launch(void* const* d_in, const int* in_sizes, int n_in,
                              void* d_out, int out_size) {
    const float* x    = (const float*)d_in[0];
    const float* cum  = (const float*)d_in[1];
    const float* g1   = (const float*)d_in[2];
    const float* g2   = (const float*)d_in[3];
    const float* Wqkv = (const float*)d_in[4];
    const float* Wo   = (const float*)d_in[5];
    const float* W1   = (const float*)d_in[6];
    const float* W2   = (const float*)d_in[7];
    const float* W3   = (const float*)d_in[8];
    const float* Wh1  = (const float*)d_in[9];
    const float* bh1  = (const float*)d_in[10];
    const float* Wh2  = (const float*)d_in[11];
    const float* bh2  = (const float*)d_in[12];

    float* outx = (float*)d_out;
    float* outh = outx + (size_t)NROWS * DMODEL;
    float* outc = outh + NROWS;

    float *h1, *qkvb, *attnb, *x1, *h2, *u, *v, *hhp;
    cudaGetSymbolAddress((void**)&h1,   g_h1);
    cudaGetSymbolAddress((void**)&qkvb, g_qkv);
    cudaGetSymbolAddress((void**)&attnb,g_attn);
    cudaGetSymbolAddress((void**)&x1,   g_x1);
    cudaGetSymbolAddress((void**)&h2,   g_h2);
    cudaGetSymbolAddress((void**)&u,    g_u);
    cudaGetSymbolAddress((void**)&v,    g_v);
    cudaGetSymbolAddress((void**)&hhp,  g_hh);

    const int gemm_smem = 2 * STAGE * sizeof(float);     // 71680 B
    cudaFuncSetAttribute(gemm_tc<0,1,1>, cudaFuncAttributeMaxDynamicSharedMemorySize, gemm_smem);
    cudaFuncSetAttribute(gemm_tc<1,1,1>, cudaFuncAttributeMaxDynamicSharedMemorySize, gemm_smem);
    cudaFuncSetAttribute(gemm_tc<0,1,0>, cudaFuncAttributeMaxDynamicSharedMemorySize, gemm_smem);
    cudaFuncSetAttribute(gemm_tc<1,0,1>, cudaFuncAttributeMaxDynamicSharedMemorySize, gemm_smem);
    cudaFuncSetAttribute(gemm_tc<2,1,1>, cudaFuncAttributeMaxDynamicSharedMemorySize, gemm_smem);

    const int attn_smem = 4 * 64 * 65 * sizeof(float);   // 66560 B
    cudaFuncSetAttribute(attn_kernel, cudaFuncAttributeMaxDynamicSharedMemorySize, attn_smem);

    // 1. h1 = rmsnorm(x, g1)
    rmsnorm_kernel<<<NROWS, 256>>>(x, g1, h1);
    // 2. qkv = h1 @ Wqkv   (M=4096 K=1024 N=3072; aligned both sides)
    gemm_tc<0,1,1><<<dim3(3 * DMODEL / 128, NROWS / 128), 256, gemm_smem>>>(
        h1, Wqkv, qkvb, nullptr, NROWS, DMODEL, 3 * DMODEL);
    // 3. attention
    attn_kernel<<<dim3(SEQ / 64, BATCH * NHEAD), 256, attn_smem>>>(qkvb, attnb);
    // 4. x1 = x + attn @ Wo   (K=1024 N=1024)
    gemm_tc<1,1,1><<<dim3(DMODEL / 128, NROWS / 128), 256, gemm_smem>>>(
        attnb, Wo, x1, x, NROWS, DMODEL, DMODEL);
    // 5. h2 = rmsnorm(x1, g2)
    rmsnorm_kernel<<<NROWS, 256>>>(x1, g2, h2);
    // 6. u = h2 @ W1, v = h2 @ W2   (N=2730 ragged -> BVEC=0)
    gemm_tc<0,1,0><<<dim3((DFF + 127) / 128, NROWS / 128), 256, gemm_smem>>>(
        h2, W1, u, nullptr, NROWS, DMODEL, DFF);
    gemm_tc<0,1,0><<<dim3((DFF + 127) / 128, NROWS / 128), 256, gemm_smem>>>(
        h2, W2, v, nullptr, NROWS, DMODEL, DFF);
    // 7. u = silu(u) * v   (float4)
    {
        int n4 = NROWS * DFF / 4;
        swiglu_kernel<<<(n4 + 255) / 256, 256>>>((float4*)u, (const float4*)v, n4);
    }
    // 8. final x = x1 + u @ W3 -> straight into d_out  (K=2730 ragged -> AVEC=0)
    gemm_tc<1,0,1><<<dim3(DMODEL / 128, NROWS / 128), 256, gemm_smem>>>(
        u, W3, outx, x1, NROWS, DFF, DMODEL);
    // 9. hh = gelu(x @ Wh1 + bh1)   (N=256)
    gemm_tc<2,1,1><<<dim3(DHALT / 128, NROWS / 128), 256, gemm_smem>>>(
        outx, Wh1, hhp, bh1, NROWS, DMODEL, DHALT);
    // 10. halt probs + cum update
    halt_kernel<<<NROWS, 256>>>(hhp, Wh2, bh2, cum, outh, outc);
}

// round 8
// speedup vs baseline: 3.0193x; 1.1850x over previous
#include <cuda_runtime.h>
#include <math.h>
#include <stdint.h>

#define DMODEL 1024
#define NHEAD  16
#define HDIM   64
#define DFF    2730
#define DHALT  256
#define BATCH  2
#define SEQ    2048
#define NROWS  (BATCH*SEQ)   // 4096

// ---------------- scratch (static device globals: allocation-guard safe) ---------
__device__ float g_h1[(size_t)NROWS*DMODEL];
__device__ float g_qkv[(size_t)NROWS*3*DMODEL];
__device__ float g_attn[(size_t)NROWS*DMODEL];
__device__ float g_x1[(size_t)NROWS*DMODEL];
__device__ float g_h2[(size_t)NROWS*DMODEL];
__device__ float g_u[(size_t)NROWS*DFF];
__device__ float g_v[(size_t)NROWS*DFF];
__device__ float g_hh[(size_t)NROWS*DHALT];

// ---------------- rmsnorm: one block per row --------------------------------
__global__ void rmsnorm_kernel(const float* __restrict__ x, const float* __restrict__ g,
                               float* __restrict__ y) {
    int row = blockIdx.x;
    const float* xr = x + (size_t)row * DMODEL;
    int t = threadIdx.x;
    float v[4];
    float ss = 0.f;
#pragma unroll
    for (int i = 0; i < 4; i++) { v[i] = xr[t + i * 256]; ss += v[i] * v[i]; }
    for (int off = 16; off; off >>= 1) ss += __shfl_xor_sync(0xffffffffu, ss, off);
    __shared__ float red[8];
    if ((t & 31) == 0) red[t >> 5] = ss;
    __syncthreads();
    if (t < 8) {
        float s2 = red[t];
        for (int off = 4; off; off >>= 1) s2 += __shfl_xor_sync(0xffu, s2, off);
        if (t == 0) red[0] = s2;
    }
    __syncthreads();
    float inv = rsqrtf(red[0] * (1.0f / DMODEL) + 1e-6f);
    float* yr = y + (size_t)row * DMODEL;
#pragma unroll
    for (int i = 0; i < 4; i++) {
        int c = t + i * 256;
        yr[c] = v[i] * inv * g[c];
    }
}

// ---------------- async-copy + mma helpers -----------------------------------
__device__ __forceinline__ uint32_t s2u(const void* p) {
    return (uint32_t)__cvta_generic_to_shared(p);
}
__device__ __forceinline__ void cp16(uint32_t d, const void* s) {
    asm volatile("cp.async.cg.shared.global [%0], [%1], 16;" :: "r"(d), "l"(s));
}
__device__ __forceinline__ void cp4(uint32_t d, const void* s) {
    asm volatile("cp.async.ca.shared.global [%0], [%1], 4;" :: "r"(d), "l"(s));
}
__device__ __forceinline__ void cp_commit() {
    asm volatile("cp.async.commit_group;");
}
__device__ __forceinline__ void mma_tf32(float c[4], const uint32_t a[4], const uint32_t b[2]) {
    asm volatile(
        "mma.sync.aligned.m16n8k8.row.col.f32.tf32.tf32.f32 "
        "{%0,%1,%2,%3}, {%4,%5,%6,%7}, {%8,%9}, {%0,%1,%2,%3};"
        : "+f"(c[0]), "+f"(c[1]), "+f"(c[2]), "+f"(c[3])
        : "r"(a[0]), "r"(a[1]), "r"(a[2]), "r"(a[3]), "r"(b[0]), "r"(b[1]));
}
__device__ __forceinline__ float tf32r(float x) {   // round-to-nearest tf32
    uint32_t y;
    asm("cvt.rna.tf32.f32 %0, %1;" : "=r"(y) : "f"(x));
    return __uint_as_float(y);
}

// ---------------- TF32 tensor-core GEMM v2 (unchanged, passing) --------------
#define AS_STRIDE 36
#define BS_STRIDE 136
#define A_TILE (128 * AS_STRIDE)
#define B_TILE (32 * BS_STRIDE)
#define STAGE  (A_TILE + B_TILE)

template <int MODE, int AVEC, int BVEC>
__global__ void __launch_bounds__(256) gemm_tc(const float* __restrict__ A,
                                               const float* __restrict__ Bm,
                                               float* __restrict__ C,
                                               const float* __restrict__ E,
                                               int M, int K, int N) {
    extern __shared__ float smem[];
    int tid = threadIdx.x;
    int w = tid >> 5, lane = tid & 31;
    int warpM = w >> 2, warpN = w & 3;
    int group = lane >> 2, tig = lane & 3;
    int m0 = blockIdx.y * 128, n0 = blockIdx.x * 128;

    auto load_tile = [&](int k0, int stg) {
        float* sA = smem + stg * STAGE;
        float* sB = sA + A_TILE;
        if (AVEC) {
#pragma unroll
            for (int i = 0; i < 4; i++) {
                int c = i * 256 + tid;
                int m = c >> 3, k4 = (c & 7) * 4;
                float* dp = sA + m * AS_STRIDE + k4;
                const float* sp = A + (size_t)(m0 + m) * K + k0 + k4;
                if (k0 + k4 + 4 <= K) cp16(s2u(dp), sp);
                else {
#pragma unroll
                    for (int e = 0; e < 4; e++) dp[e] = (k0 + k4 + e < K) ? sp[e] : 0.f;
                }
            }
        } else {
#pragma unroll
            for (int i = 0; i < 16; i++) {
                int c = i * 256 + tid;
                int m = c >> 5, kk = c & 31;
                float* dp = sA + m * AS_STRIDE + kk;
                if (k0 + kk < K) cp4(s2u(dp), A + (size_t)(m0 + m) * K + k0 + kk);
                else *dp = 0.f;
            }
        }
        if (BVEC) {
#pragma unroll
            for (int i = 0; i < 4; i++) {
                int c = i * 256 + tid;
                int kk = c >> 5, n4 = (c & 31) * 4;
                float* dp = sB + kk * BS_STRIDE + n4;
                if (k0 + kk < K) cp16(s2u(dp), Bm + (size_t)(k0 + kk) * N + n0 + n4);
                else { dp[0] = 0.f; dp[1] = 0.f; dp[2] = 0.f; dp[3] = 0.f; }
            }
        } else {
#pragma unroll
            for (int i = 0; i < 16; i++) {
                int c = i * 256 + tid;
                int kk = c >> 7, n = c & 127;
                float* dp = sB + kk * BS_STRIDE + n;
                if (k0 + kk < K && n0 + n < N) cp4(s2u(dp), Bm + (size_t)(k0 + kk) * N + n0 + n);
                else *dp = 0.f;
            }
        }
    };

    float acc[4][4][4];
#pragma unroll
    for (int mi = 0; mi < 4; mi++)
#pragma unroll
        for (int ni = 0; ni < 4; ni++)
#pragma unroll
            for (int r = 0; r < 4; r++) acc[mi][ni][r] = 0.f;

    int ntiles = (K + 31) / 32;
    load_tile(0, 0);
    cp_commit();

    for (int t = 0; t < ntiles; t++) {
        if (t + 1 < ntiles) {
            load_tile((t + 1) * 32, (t + 1) & 1);
            cp_commit();
            asm volatile("cp.async.wait_group 1;");
        } else {
            asm volatile("cp.async.wait_group 0;");
        }
        __syncthreads();

        const float* sA = smem + (t & 1) * STAGE;
        const float* sB = sA + A_TILE;
#pragma unroll
        for (int ks = 0; ks < 32; ks += 8) {
            uint32_t afrag[4][4], bfrag[4][2];
#pragma unroll
            for (int mi = 0; mi < 4; mi++) {
                int rm = warpM * 64 + mi * 16;
                afrag[mi][0] = __float_as_uint(sA[(rm + group)     * AS_STRIDE + ks + tig]);
                afrag[mi][1] = __float_as_uint(sA[(rm + group + 8) * AS_STRIDE + ks + tig]);
                afrag[mi][2] = __float_as_uint(sA[(rm + group)     * AS_STRIDE + ks + tig + 4]);
                afrag[mi][3] = __float_as_uint(sA[(rm + group + 8) * AS_STRIDE + ks + tig + 4]);
            }
#pragma unroll
            for (int ni = 0; ni < 4; ni++) {
                int cn = warpN * 32 + ni * 8;
                bfrag[ni][0] = __float_as_uint(sB[(ks + tig)     * BS_STRIDE + cn + group]);
                bfrag[ni][1] = __float_as_uint(sB[(ks + tig + 4) * BS_STRIDE + cn + group]);
            }
#pragma unroll
            for (int mi = 0; mi < 4; mi++)
#pragma unroll
                for (int ni = 0; ni < 4; ni++)
                    mma_tf32(acc[mi][ni], afrag[mi], bfrag[ni]);
        }
        __syncthreads();
    }

#pragma unroll
    for (int mi = 0; mi < 4; mi++) {
#pragma unroll
        for (int ni = 0; ni < 4; ni++) {
#pragma unroll
            for (int r = 0; r < 4; r++) {
                int row = m0 + warpM * 64 + mi * 16 + group + (r >> 1) * 8;
                int col = n0 + warpN * 32 + ni * 8 + tig * 2 + (r & 1);
                if (row >= M || col >= N) continue;
                float val = acc[mi][ni][r];
                if (MODE == 1) val += E[(size_t)row * N + col];
                if (MODE == 2) {
                    val += E[col];
                    val = 0.5f * val * (1.f + erff(val * 0.70710678118654752f));
                }
                C[(size_t)row * N + col] = val;
            }
        }
    }
}

// ---------------- tf32 tensor-core flash attention ---------------------------
// BQ=BK=64, HD=64. 128 threads = 4 warps; warp w owns rows [w*16, w*16+16).
// S = Q K^T via mma (K transposed in smem), online softmax on fragments,
// P -> warp-private smem (tf32 rna), O += P V via mma (V natural layout).
#define QS_ST 68   // %32 == 4 -> conflict-free a-frag loads
#define KT_ST 72   // %32 == 8 -> conflict-free b-frag loads
#define VS_ST 72
#define PS_ST 68
#define ATTN_SMEM ((64*QS_ST + 64*KT_ST + 64*VS_ST + 64*PS_ST) * 4)  // 71680 B

__global__ void __launch_bounds__(128) attn_tc(const float* __restrict__ qkv,
                                               float* __restrict__ out) {
    extern __shared__ float sm[];
    float* Qs = sm;                  // [m][d]
    float* KT = Qs + 64 * QS_ST;     // [d][n]  (K transposed)
    float* Vs = KT + 64 * KT_ST;     // [j][n]
    float* Ps = Vs + 64 * VS_ST;     // [m][j]
    int tid = threadIdx.x;
    int warp = tid >> 5, lane = tid & 31;
    int group = lane >> 2, tig = lane & 3;
    int bh = blockIdx.y;
    int b = bh >> 4, h = bh & 15;
    int qt0 = blockIdx.x * 64;
    size_t base = (size_t)b * SEQ * 3072;
    int rm = warp * 16;

    // load Q tile (rna-rounded)
#pragma unroll
    for (int i = 0; i < 8; i++) {
        int e = i * 128 + tid;
        int r = e >> 4, dq = e & 15;
        float4 q = *(const float4*)&qkv[base + (size_t)(qt0 + r) * 3072 + h * 64 + dq * 4];
        float* d = &Qs[r * QS_ST + dq * 4];
        d[0] = tf32r(q.x); d[1] = tf32r(q.y); d[2] = tf32r(q.z); d[3] = tf32r(q.w);
    }

    float o[8][4];
    float m0 = -1e30f, m1 = -1e30f, l0 = 0.f, l1 = 0.f;
#pragma unroll
    for (int ni = 0; ni < 8; ni++)
#pragma unroll
        for (int r = 0; r < 4; r++) o[ni][r] = 0.f;

    int jt_max = blockIdx.x;
    for (int jt = 0; jt <= jt_max; jt++) {
        int j0 = jt * 64;
        __syncthreads();   // prior tile's KT/Vs reads done (covers Q load on jt=0)
        // load K (transposed) and V (natural), rna-rounded
#pragma unroll
        for (int i = 0; i < 8; i++) {
            int e = i * 128 + tid;
            int r = e >> 4, dq = e & 15;
            float4 k4 = *(const float4*)&qkv[base + (size_t)(j0 + r) * 3072 + 1024 + h * 64 + dq * 4];
            KT[(dq * 4 + 0) * KT_ST + r] = tf32r(k4.x);
            KT[(dq * 4 + 1) * KT_ST + r] = tf32r(k4.y);
            KT[(dq * 4 + 2) * KT_ST + r] = tf32r(k4.z);
            KT[(dq * 4 + 3) * KT_ST + r] = tf32r(k4.w);
            float4 v4 = *(const float4*)&qkv[base + (size_t)(j0 + r) * 3072 + 2048 + h * 64 + dq * 4];
            float4 vt;
            vt.x = tf32r(v4.x); vt.y = tf32r(v4.y); vt.z = tf32r(v4.z); vt.w = tf32r(v4.w);
            *(float4*)&Vs[r * VS_ST + dq * 4] = vt;
        }
        __syncthreads();

        // ---- S = Q K^T ----
        float s[8][4];
#pragma unroll
        for (int ni = 0; ni < 8; ni++)
#pragma unroll
            for (int r = 0; r < 4; r++) s[ni][r] = 0.f;
#pragma unroll
        for (int ks = 0; ks < 64; ks += 8) {
            uint32_t a[4];
            a[0] = __float_as_uint(Qs[(rm + group)     * QS_ST + ks + tig]);
            a[1] = __float_as_uint(Qs[(rm + group + 8) * QS_ST + ks + tig]);
            a[2] = __float_as_uint(Qs[(rm + group)     * QS_ST + ks + tig + 4]);
            a[3] = __float_as_uint(Qs[(rm + group + 8) * QS_ST + ks + tig + 4]);
#pragma unroll
            for (int ni = 0; ni < 8; ni++) {
                uint32_t bb[2];
                bb[0] = __float_as_uint(KT[(ks + tig)     * KT_ST + ni * 8 + group]);
                bb[1] = __float_as_uint(KT[(ks + tig + 4) * KT_ST + ni * 8 + group]);
                mma_tf32(s[ni], a, bb);
            }
        }
        // scale + causal mask
        int row0 = qt0 + rm + group;
        bool diag = (jt == jt_max);
#pragma unroll
        for (int ni = 0; ni < 8; ni++) {
#pragma unroll
            for (int r = 0; r < 4; r++) s[ni][r] *= 0.125f;
            if (diag) {
                int c0 = j0 + ni * 8 + 2 * tig;
                if (c0     > row0)     s[ni][0] = -1e30f;
                if (c0 + 1 > row0)     s[ni][1] = -1e30f;
                if (c0     > row0 + 8) s[ni][2] = -1e30f;
                if (c0 + 1 > row0 + 8) s[ni][3] = -1e30f;
            }
        }
        // ---- online softmax (rows g and g+8; reduce over 4-lane quad) ----
        float tm0 = -1e30f, tm1 = -1e30f;
#pragma unroll
        for (int ni = 0; ni < 8; ni++) {
            tm0 = fmaxf(tm0, fmaxf(s[ni][0], s[ni][1]));
            tm1 = fmaxf(tm1, fmaxf(s[ni][2], s[ni][3]));
        }
        tm0 = fmaxf(tm0, __shfl_xor_sync(0xffffffffu, tm0, 1));
        tm0 = fmaxf(tm0, __shfl_xor_sync(0xffffffffu, tm0, 2));
        tm1 = fmaxf(tm1, __shfl_xor_sync(0xffffffffu, tm1, 1));
        tm1 = fmaxf(tm1, __shfl_xor_sync(0xffffffffu, tm1, 2));
        float nm0 = fmaxf(m0, tm0), nm1 = fmaxf(m1, tm1);
        float f0 = __expf(m0 - nm0), f1 = __expf(m1 - nm1);
        float rs0 = 0.f, rs1 = 0.f;
#pragma unroll
        for (int ni = 0; ni < 8; ni++) {
            s[ni][0] = __expf(s[ni][0] - nm0);
            s[ni][1] = __expf(s[ni][1] - nm0);
            s[ni][2] = __expf(s[ni][2] - nm1);
            s[ni][3] = __expf(s[ni][3] - nm1);
            rs0 += s[ni][0] + s[ni][1];
            rs1 += s[ni][2] + s[ni][3];
        }
        rs0 += __shfl_xor_sync(0xffffffffu, rs0, 1);
        rs0 += __shfl_xor_sync(0xffffffffu, rs0, 2);
        rs1 += __shfl_xor_sync(0xffffffffu, rs1, 1);
        rs1 += __shfl_xor_sync(0xffffffffu, rs1, 2);
        l0 = l0 * f0 + rs0; l1 = l1 * f1 + rs1;
        m0 = nm0; m1 = nm1;
#pragma unroll
        for (int ni = 0; ni < 8; ni++) {
            o[ni][0] *= f0; o[ni][1] *= f0; o[ni][2] *= f1; o[ni][3] *= f1;
        }
        // ---- P -> smem (warp-private rows), then O += P V ----
#pragma unroll
        for (int ni = 0; ni < 8; ni++) {
            int c = ni * 8 + 2 * tig;
            Ps[(rm + group)     * PS_ST + c    ] = tf32r(s[ni][0]);
            Ps[(rm + group)     * PS_ST + c + 1] = tf32r(s[ni][1]);
            Ps[(rm + group + 8) * PS_ST + c    ] = tf32r(s[ni][2]);
            Ps[(rm + group + 8) * PS_ST + c + 1] = tf32r(s[ni][3]);
        }
        __syncwarp();
#pragma unroll
        for (int ks = 0; ks < 64; ks += 8) {
            uint32_t a[4];
            a[0] = __float_as_uint(Ps[(rm + group)     * PS_ST + ks + tig]);
            a[1] = __float_as_uint(Ps[(rm + group + 8) * PS_ST + ks + tig]);
            a[2] = __float_as_uint(Ps[(rm + group)     * PS_ST + ks + tig + 4]);
            a[3] = __float_as_uint(Ps[(rm + group + 8) * PS_ST + ks + tig + 4]);
#pragma unroll
            for (int ni = 0; ni < 8; ni++) {
                uint32_t bb[2];
                bb[0] = __float_as_uint(Vs[(ks + tig)     * VS_ST + ni * 8 + group]);
                bb[1] = __float_as_uint(Vs[(ks + tig + 4) * VS_ST + ni * 8 + group]);
                mma_tf32(o[ni], a, bb);
            }
        }
        __syncwarp();   // Ps reads done before next tile's overwrite
    }

    // ---- write O (rows qt0+rm+group and +8), cols = head dims ----
    float inv0 = 1.f / l0, inv1 = 1.f / l1;
    int r0 = qt0 + rm + group;
#pragma unroll
    for (int ni = 0; ni < 8; ni++) {
        int c = ni * 8 + 2 * tig;
        float2 w0 = make_float2(o[ni][0] * inv0, o[ni][1] * inv0);
        float2 w1 = make_float2(o[ni][2] * inv1, o[ni][3] * inv1);
        *(float2*)&out[(size_t)(b * SEQ + r0)     * DMODEL + h * 64 + c] = w0;
        *(float2*)&out[(size_t)(b * SEQ + r0 + 8) * DMODEL + h * 64 + c] = w1;
    }
}

// ---------------- swiglu elementwise (float4): u = silu(u) * v ---------------
__global__ void swiglu_kernel(float4* __restrict__ u, const float4* __restrict__ v, int n4) {
    int i = blockIdx.x * blockDim.x + threadIdx.x;
    if (i < n4) {
        float4 a = u[i], b = v[i];
        a.x = a.x / (1.f + expf(-a.x)) * b.x;
        a.y = a.y / (1.f + expf(-a.y)) * b.y;
        a.z = a.z / (1.f + expf(-a.z)) * b.z;
        a.w = a.w / (1.f + expf(-a.w)) * b.w;
        u[i] = a;
    }
}

// ---------------- halt head --------------------------------------------------
__global__ void halt_kernel(const float* __restrict__ hh, const float* __restrict__ Wh2,
                            const float* __restrict__ bh2, const float* __restrict__ cum,
                            float* __restrict__ halt_out, float* __restrict__ cum_out) {
    int row = blockIdx.x;
    int t = threadIdx.x;
    float p = hh[(size_t)row * DHALT + t] * Wh2[t];
    for (int off = 16; off; off >>= 1) p += __shfl_xor_sync(0xffffffffu, p, off);
    __shared__ float red[8];
    if ((t & 31) == 0) red[t >> 5] = p;
    __syncthreads();
    if (t == 0) {
        float sum = red[0] + red[1] + red[2] + red[3] + red[4] + red[5] + red[6] + red[7] + bh2[0];
        float hp = 1.f / (1.f + expf(-sum));
        float c = cum[row];
        float still = (c < 0.99f) ? 1.f : 0.f;
        halt_out[row] = hp;
        cum_out[row] = c + hp * still;
    }
}

// ---------------- launch ------------------------------------------------------
extern "C" void kernel_launch(void* const* d_in, const int* in_sizes, int n_in,
                              void* d_out, int out_size) {
    const float* x    = (const float*)d_in[0];
    const float* cum  = (const float*)d_in[1];
    const float* g1   = (const float*)d_in[2];
    const float* g2   = (const float*)d_in[3];
    const float* Wqkv = (const float*)d_in[4];
    const float* Wo   = (const float*)d_in[5];
    const float* W1   = (const float*)d_in[6];
    const float* W2   = (const float*)d_in[7];
    const float* W3   = (const float*)d_in[8];
    const float* Wh1  = (const float*)d_in[9];
    const float* bh1  = (const float*)d_in[10];
    const float* Wh2  = (const float*)d_in[11];
    const float* bh2  = (const float*)d_in[12];

    float* outx = (float*)d_out;
    float* outh = outx + (size_t)NROWS * DMODEL;
    float* outc = outh + NROWS;

    float *h1, *qkvb, *attnb, *x1, *h2, *u, *v, *hhp;
    cudaGetSymbolAddress((void**)&h1,   g_h1);
    cudaGetSymbolAddress((void**)&qkvb, g_qkv);
    cudaGetSymbolAddress((void**)&attnb,g_attn);
    cudaGetSymbolAddress((void**)&x1,   g_x1);
    cudaGetSymbolAddress((void**)&h2,   g_h2);
    cudaGetSymbolAddress((void**)&u,    g_u);
    cudaGetSymbolAddress((void**)&v,    g_v);
    cudaGetSymbolAddress((void**)&hhp,  g_hh);

    const int gemm_smem = 2 * STAGE * sizeof(float);     // 71680 B
    cudaFuncSetAttribute(gemm_tc<0,1,1>, cudaFuncAttributeMaxDynamicSharedMemorySize, gemm_smem);
    cudaFuncSetAttribute(gemm_tc<1,1,1>, cudaFuncAttributeMaxDynamicSharedMemorySize, gemm_smem);
    cudaFuncSetAttribute(gemm_tc<0,1,0>, cudaFuncAttributeMaxDynamicSharedMemorySize, gemm_smem);
    cudaFuncSetAttribute(gemm_tc<1,0,1>, cudaFuncAttributeMaxDynamicSharedMemorySize, gemm_smem);
    cudaFuncSetAttribute(gemm_tc<2,1,1>, cudaFuncAttributeMaxDynamicSharedMemorySize, gemm_smem);
    cudaFuncSetAttribute(attn_tc, cudaFuncAttributeMaxDynamicSharedMemorySize, ATTN_SMEM);

    // 1. h1 = rmsnorm(x, g1)
    rmsnorm_kernel<<<NROWS, 256>>>(x, g1, h1);
    // 2. qkv = h1 @ Wqkv
    gemm_tc<0,1,1><<<dim3(3 * DMODEL / 128, NROWS / 128), 256, gemm_smem>>>(
        h1, Wqkv, qkvb, nullptr, NROWS, DMODEL, 3 * DMODEL);
    // 3. attention (tf32 tensor cores)
    attn_tc<<<dim3(SEQ / 64, BATCH * NHEAD), 128, ATTN_SMEM>>>(qkvb, attnb);
    // 4. x1 = x + attn @ Wo
    gemm_tc<1,1,1><<<dim3(DMODEL / 128, NROWS / 128), 256, gemm_smem>>>(
        attnb, Wo, x1, x, NROWS, DMODEL, DMODEL);
    // 5. h2 = rmsnorm(x1, g2)
    rmsnorm_kernel<<<NROWS, 256>>>(x1, g2, h2);
    // 6. u = h2 @ W1, v = h2 @ W2
    gemm_tc<0,1,0><<<dim3((DFF + 127) / 128, NROWS / 128), 256, gemm_smem>>>(
        h2, W1, u, nullptr, NROWS, DMODEL, DFF);
    gemm_tc<0,1,0><<<dim3((DFF + 127) / 128, NROWS / 128), 256, gemm_smem>>>(
        h2, W2, v, nullptr, NROWS, DMODEL, DFF);
    // 7. u = silu(u) * v
    {
        int n4 = NROWS * DFF / 4;
        swiglu_kernel<<<(n4 + 255) / 256, 256>>>((float4*)u, (const float4*)v, n4);
    }
    // 8. final x = x1 + u @ W3 -> d_out
    gemm_tc<1,0,1><<<dim3(DMODEL / 128, NROWS / 128), 256, gemm_smem>>>(
        u, W3, outx, x1, NROWS, DFF, DMODEL);
    // 9. hh = gelu(x @ Wh1 + bh1)
    gemm_tc<2,1,1><<<dim3(DHALT / 128, NROWS / 128), 256, gemm_smem>>>(
        outx, Wh1, hhp, bh1, NROWS, DMODEL, DHALT);
    // 10. halt probs + cum update
    halt_kernel<<<NROWS, 256>>>(hhp, Wh2, bh2, cum, outh, outc);
}

// round 9
// speedup vs baseline: 3.2992x; 1.0927x over previous
#include <cuda_runtime.h>
#include <math.h>
#include <stdint.h>

#define DMODEL 1024
#define NHEAD  16
#define HDIM   64
#define DFF    2730
#define DHALT  256
#define BATCH  2
#define SEQ    2048
#define NROWS  (BATCH*SEQ)   // 4096

// ---------------- scratch (static device globals: allocation-guard safe) ---------
__device__ float g_h1[(size_t)NROWS*DMODEL];
__device__ float g_qkv[(size_t)NROWS*3*DMODEL];
__device__ float g_attn[(size_t)NROWS*DMODEL];
__device__ float g_x1[(size_t)NROWS*DMODEL];
__device__ float g_h2[(size_t)NROWS*DMODEL];
__device__ float g_u[(size_t)NROWS*DFF];
__device__ float g_v[(size_t)NROWS*DFF];
__device__ float g_hh[(size_t)NROWS*DHALT];

// ---------------- rmsnorm: one block per row --------------------------------
__global__ void rmsnorm_kernel(const float* __restrict__ x, const float* __restrict__ g,
                               float* __restrict__ y) {
    int row = blockIdx.x;
    const float* xr = x + (size_t)row * DMODEL;
    int t = threadIdx.x;
    float v[4];
    float ss = 0.f;
#pragma unroll
    for (int i = 0; i < 4; i++) { v[i] = xr[t + i * 256]; ss += v[i] * v[i]; }
    for (int off = 16; off; off >>= 1) ss += __shfl_xor_sync(0xffffffffu, ss, off);
    __shared__ float red[8];
    if ((t & 31) == 0) red[t >> 5] = ss;
    __syncthreads();
    if (t < 8) {
        float s2 = red[t];
        for (int off = 4; off; off >>= 1) s2 += __shfl_xor_sync(0xffu, s2, off);
        if (t == 0) red[0] = s2;
    }
    __syncthreads();
    float inv = rsqrtf(red[0] * (1.0f / DMODEL) + 1e-6f);
    float* yr = y + (size_t)row * DMODEL;
#pragma unroll
    for (int i = 0; i < 4; i++) {
        int c = t + i * 256;
        yr[c] = v[i] * inv * g[c];
    }
}

// ---------------- async-copy + mma helpers -----------------------------------
__device__ __forceinline__ uint32_t s2u(const void* p) {
    return (uint32_t)__cvta_generic_to_shared(p);
}
__device__ __forceinline__ void cp16(uint32_t d, const void* s) {
    asm volatile("cp.async.cg.shared.global [%0], [%1], 16;" :: "r"(d), "l"(s));
}
__device__ __forceinline__ void cp4(uint32_t d, const void* s) {
    asm volatile("cp.async.ca.shared.global [%0], [%1], 4;" :: "r"(d), "l"(s));
}
__device__ __forceinline__ void cp_commit() {
    asm volatile("cp.async.commit_group;");
}
__device__ __forceinline__ void mma_tf32(float c[4], const uint32_t a[4], const uint32_t b[2]) {
    asm volatile(
        "mma.sync.aligned.m16n8k8.row.col.f32.tf32.tf32.f32 "
        "{%0,%1,%2,%3}, {%4,%5,%6,%7}, {%8,%9}, {%0,%1,%2,%3};"
        : "+f"(c[0]), "+f"(c[1]), "+f"(c[2]), "+f"(c[3])
        : "r"(a[0]), "r"(a[1]), "r"(a[2]), "r"(a[3]), "r"(b[0]), "r"(b[1]));
}
__device__ __forceinline__ float tf32r(float x) {   // round-to-nearest tf32
    uint32_t y;
    asm("cvt.rna.tf32.f32 %0, %1;" : "=r"(y) : "f"(x));
    return __uint_as_float(y);
}

// ---------------- TF32 tensor-core GEMM v3: 3-stage, 1 barrier/ktile ---------
#define AS_STRIDE 36
#define BS_STRIDE 136
#define A_TILE (128 * AS_STRIDE)
#define B_TILE (32 * BS_STRIDE)
#define STAGE  (A_TILE + B_TILE)
#define NSTAGE 3
#define GEMM_SMEM (NSTAGE * STAGE * sizeof(float))   // 107520 B

template <int MODE, int AVEC, int BVEC>
__global__ void __launch_bounds__(256) gemm_tc(const float* __restrict__ A,
                                               const float* __restrict__ Bm,
                                               float* __restrict__ C,
                                               const float* __restrict__ E,
                                               int M, int K, int N) {
    extern __shared__ float smem[];
    int tid = threadIdx.x;
    int w = tid >> 5, lane = tid & 31;
    int warpM = w >> 2, warpN = w & 3;
    int group = lane >> 2, tig = lane & 3;
    int m0 = blockIdx.y * 128, n0 = blockIdx.x * 128;

    auto load_tile = [&](int k0, int stg) {
        float* sA = smem + stg * STAGE;
        float* sB = sA + A_TILE;
        if (AVEC) {
#pragma unroll
            for (int i = 0; i < 4; i++) {
                int c = i * 256 + tid;
                int m = c >> 3, k4 = (c & 7) * 4;
                float* dp = sA + m * AS_STRIDE + k4;
                const float* sp = A + (size_t)(m0 + m) * K + k0 + k4;
                if (k0 + k4 + 4 <= K) cp16(s2u(dp), sp);
                else {
#pragma unroll
                    for (int e = 0; e < 4; e++) dp[e] = (k0 + k4 + e < K) ? sp[e] : 0.f;
                }
            }
        } else {
#pragma unroll
            for (int i = 0; i < 16; i++) {
                int c = i * 256 + tid;
                int m = c >> 5, kk = c & 31;
                float* dp = sA + m * AS_STRIDE + kk;
                if (k0 + kk < K) cp4(s2u(dp), A + (size_t)(m0 + m) * K + k0 + kk);
                else *dp = 0.f;
            }
        }
        if (BVEC) {
#pragma unroll
            for (int i = 0; i < 4; i++) {
                int c = i * 256 + tid;
                int kk = c >> 5, n4 = (c & 31) * 4;
                float* dp = sB + kk * BS_STRIDE + n4;
                if (k0 + kk < K) cp16(s2u(dp), Bm + (size_t)(k0 + kk) * N + n0 + n4);
                else { dp[0] = 0.f; dp[1] = 0.f; dp[2] = 0.f; dp[3] = 0.f; }
            }
        } else {
#pragma unroll
            for (int i = 0; i < 16; i++) {
                int c = i * 256 + tid;
                int kk = c >> 7, n = c & 127;
                float* dp = sB + kk * BS_STRIDE + n;
                if (k0 + kk < K && n0 + n < N) cp4(s2u(dp), Bm + (size_t)(k0 + kk) * N + n0 + n);
                else *dp = 0.f;
            }
        }
    };

    float acc[4][4][4];
#pragma unroll
    for (int mi = 0; mi < 4; mi++)
#pragma unroll
        for (int ni = 0; ni < 4; ni++)
#pragma unroll
            for (int r = 0; r < 4; r++) acc[mi][ni][r] = 0.f;

    int ntiles = (K + 31) / 32;
    load_tile(0, 0);
    cp_commit();
    if (ntiles > 1) { load_tile(32, 1); cp_commit(); }

    for (int t = 0; t < ntiles; t++) {
        // ensure tile t landed (loads complete in commit order)
        if (t + 1 < ntiles) asm volatile("cp.async.wait_group 1;");
        else                asm volatile("cp.async.wait_group 0;");
        __syncthreads();   // single barrier per ktile: all warps past compute t-1
        if (t + 2 < ntiles) {
            load_tile((t + 2) * 32, (t + 2) % NSTAGE);   // buf != t%3, != (t+1)%3
            cp_commit();
        }

        const float* sA = smem + (t % NSTAGE) * STAGE;
        const float* sB = sA + A_TILE;
#pragma unroll
        for (int ks = 0; ks < 32; ks += 8) {
            uint32_t afrag[4][4], bfrag[4][2];
#pragma unroll
            for (int mi = 0; mi < 4; mi++) {
                int rm = warpM * 64 + mi * 16;
                afrag[mi][0] = __float_as_uint(sA[(rm + group)     * AS_STRIDE + ks + tig]);
                afrag[mi][1] = __float_as_uint(sA[(rm + group + 8) * AS_STRIDE + ks + tig]);
                afrag[mi][2] = __float_as_uint(sA[(rm + group)     * AS_STRIDE + ks + tig + 4]);
                afrag[mi][3] = __float_as_uint(sA[(rm + group + 8) * AS_STRIDE + ks + tig + 4]);
            }
#pragma unroll
            for (int ni = 0; ni < 4; ni++) {
                int cn = warpN * 32 + ni * 8;
                bfrag[ni][0] = __float_as_uint(sB[(ks + tig)     * BS_STRIDE + cn + group]);
                bfrag[ni][1] = __float_as_uint(sB[(ks + tig + 4) * BS_STRIDE + cn + group]);
            }
#pragma unroll
            for (int mi = 0; mi < 4; mi++)
#pragma unroll
                for (int ni = 0; ni < 4; ni++)
                    mma_tf32(acc[mi][ni], afrag[mi], bfrag[ni]);
        }
    }

    // epilogue: (c0,c1) = cols (c,c+1) @ row; (c2,c3) same cols @ row+8.
    // M is always a multiple of 128 here (M=4096); N is even -> col<N implies col+1<N.
#pragma unroll
    for (int mi = 0; mi < 4; mi++) {
        int row = m0 + warpM * 64 + mi * 16 + group;
#pragma unroll
        for (int ni = 0; ni < 4; ni++) {
            int col = n0 + warpN * 32 + ni * 8 + tig * 2;
            if (col >= N) continue;
            float2 lo = make_float2(acc[mi][ni][0], acc[mi][ni][1]);
            float2 hi = make_float2(acc[mi][ni][2], acc[mi][ni][3]);
            if (MODE == 1) {
                float2 e0 = *(const float2*)&E[(size_t)row * N + col];
                float2 e1 = *(const float2*)&E[(size_t)(row + 8) * N + col];
                lo.x += e0.x; lo.y += e0.y; hi.x += e1.x; hi.y += e1.y;
            }
            if (MODE == 2) {
                float2 bb = *(const float2*)&E[col];
                lo.x += bb.x; lo.y += bb.y; hi.x += bb.x; hi.y += bb.y;
                lo.x = 0.5f * lo.x * (1.f + erff(lo.x * 0.70710678118654752f));
                lo.y = 0.5f * lo.y * (1.f + erff(lo.y * 0.70710678118654752f));
                hi.x = 0.5f * hi.x * (1.f + erff(hi.x * 0.70710678118654752f));
                hi.y = 0.5f * hi.y * (1.f + erff(hi.y * 0.70710678118654752f));
            }
            *(float2*)&C[(size_t)row * N + col] = lo;
            *(float2*)&C[(size_t)(row + 8) * N + col] = hi;
        }
    }
}

// ---------------- tf32 tensor-core flash attention (unchanged, passing) ------
#define QS_ST 68
#define KT_ST 72
#define VS_ST 72
#define PS_ST 68
#define ATTN_SMEM ((64*QS_ST + 64*KT_ST + 64*VS_ST + 64*PS_ST) * 4)  // 71680 B

__global__ void __launch_bounds__(128) attn_tc(const float* __restrict__ qkv,
                                               float* __restrict__ out) {
    extern __shared__ float sm[];
    float* Qs = sm;
    float* KT = Qs + 64 * QS_ST;
    float* Vs = KT + 64 * KT_ST;
    float* Ps = Vs + 64 * VS_ST;
    int tid = threadIdx.x;
    int warp = tid >> 5, lane = tid & 31;
    int group = lane >> 2, tig = lane & 3;
    int bh = blockIdx.y;
    int b = bh >> 4, h = bh & 15;
    int qt0 = blockIdx.x * 64;
    size_t base = (size_t)b * SEQ * 3072;
    int rm = warp * 16;

#pragma unroll
    for (int i = 0; i < 8; i++) {
        int e = i * 128 + tid;
        int r = e >> 4, dq = e & 15;
        float4 q = *(const float4*)&qkv[base + (size_t)(qt0 + r) * 3072 + h * 64 + dq * 4];
        float* d = &Qs[r * QS_ST + dq * 4];
        d[0] = tf32r(q.x); d[1] = tf32r(q.y); d[2] = tf32r(q.z); d[3] = tf32r(q.w);
    }

    float o[8][4];
    float m0 = -1e30f, m1 = -1e30f, l0 = 0.f, l1 = 0.f;
#pragma unroll
    for (int ni = 0; ni < 8; ni++)
#pragma unroll
        for (int r = 0; r < 4; r++) o[ni][r] = 0.f;

    int jt_max = blockIdx.x;
    for (int jt = 0; jt <= jt_max; jt++) {
        int j0 = jt * 64;
        __syncthreads();
#pragma unroll
        for (int i = 0; i < 8; i++) {
            int e = i * 128 + tid;
            int r = e >> 4, dq = e & 15;
            float4 k4 = *(const float4*)&qkv[base + (size_t)(j0 + r) * 3072 + 1024 + h * 64 + dq * 4];
            KT[(dq * 4 + 0) * KT_ST + r] = tf32r(k4.x);
            KT[(dq * 4 + 1) * KT_ST + r] = tf32r(k4.y);
            KT[(dq * 4 + 2) * KT_ST + r] = tf32r(k4.z);
            KT[(dq * 4 + 3) * KT_ST + r] = tf32r(k4.w);
            float4 v4 = *(const float4*)&qkv[base + (size_t)(j0 + r) * 3072 + 2048 + h * 64 + dq * 4];
            float4 vt;
            vt.x = tf32r(v4.x); vt.y = tf32r(v4.y); vt.z = tf32r(v4.z); vt.w = tf32r(v4.w);
            *(float4*)&Vs[r * VS_ST + dq * 4] = vt;
        }
        __syncthreads();

        float s[8][4];
#pragma unroll
        for (int ni = 0; ni < 8; ni++)
#pragma unroll
            for (int r = 0; r < 4; r++) s[ni][r] = 0.f;
#pragma unroll
        for (int ks = 0; ks < 64; ks += 8) {
            uint32_t a[4];
            a[0] = __float_as_uint(Qs[(rm + group)     * QS_ST + ks + tig]);
            a[1] = __float_as_uint(Qs[(rm + group + 8) * QS_ST + ks + tig]);
            a[2] = __float_as_uint(Qs[(rm + group)     * QS_ST + ks + tig + 4]);
            a[3] = __float_as_uint(Qs[(rm + group + 8) * QS_ST + ks + tig + 4]);
#pragma unroll
            for (int ni = 0; ni < 8; ni++) {
                uint32_t bb[2];
                bb[0] = __float_as_uint(KT[(ks + tig)     * KT_ST + ni * 8 + group]);
                bb[1] = __float_as_uint(KT[(ks + tig + 4) * KT_ST + ni * 8 + group]);
                mma_tf32(s[ni], a, bb);
            }
        }
        int row0 = qt0 + rm + group;
        bool diag = (jt == jt_max);
#pragma unroll
        for (int ni = 0; ni < 8; ni++) {
#pragma unroll
            for (int r = 0; r < 4; r++) s[ni][r] *= 0.125f;
            if (diag) {
                int c0 = j0 + ni * 8 + 2 * tig;
                if (c0     > row0)     s[ni][0] = -1e30f;
                if (c0 + 1 > row0)     s[ni][1] = -1e30f;
                if (c0     > row0 + 8) s[ni][2] = -1e30f;
                if (c0 + 1 > row0 + 8) s[ni][3] = -1e30f;
            }
        }
        float tm0 = -1e30f, tm1 = -1e30f;
#pragma unroll
        for (int ni = 0; ni < 8; ni++) {
            tm0 = fmaxf(tm0, fmaxf(s[ni][0], s[ni][1]));
            tm1 = fmaxf(tm1, fmaxf(s[ni][2], s[ni][3]));
        }
        tm0 = fmaxf(tm0, __shfl_xor_sync(0xffffffffu, tm0, 1));
        tm0 = fmaxf(tm0, __shfl_xor_sync(0xffffffffu, tm0, 2));
        tm1 = fmaxf(tm1, __shfl_xor_sync(0xffffffffu, tm1, 1));
        tm1 = fmaxf(tm1, __shfl_xor_sync(0xffffffffu, tm1, 2));
        float nm0 = fmaxf(m0, tm0), nm1 = fmaxf(m1, tm1);
        float f0 = __expf(m0 - nm0), f1 = __expf(m1 - nm1);
        float rs0 = 0.f, rs1 = 0.f;
#pragma unroll
        for (int ni = 0; ni < 8; ni++) {
            s[ni][0] = __expf(s[ni][0] - nm0);
            s[ni][1] = __expf(s[ni][1] - nm0);
            s[ni][2] = __expf(s[ni][2] - nm1);
            s[ni][3] = __expf(s[ni][3] - nm1);
            rs0 += s[ni][0] + s[ni][1];
            rs1 += s[ni][2] + s[ni][3];
        }
        rs0 += __shfl_xor_sync(0xffffffffu, rs0, 1);
        rs0 += __shfl_xor_sync(0xffffffffu, rs0, 2);
        rs1 += __shfl_xor_sync(0xffffffffu, rs1, 1);
        rs1 += __shfl_xor_sync(0xffffffffu, rs1, 2);
        l0 = l0 * f0 + rs0; l1 = l1 * f1 + rs1;
        m0 = nm0; m1 = nm1;
#pragma unroll
        for (int ni = 0; ni < 8; ni++) {
            o[ni][0] *= f0; o[ni][1] *= f0; o[ni][2] *= f1; o[ni][3] *= f1;
        }
#pragma unroll
        for (int ni = 0; ni < 8; ni++) {
            int c = ni * 8 + 2 * tig;
            Ps[(rm + group)     * PS_ST + c    ] = tf32r(s[ni][0]);
            Ps[(rm + group)     * PS_ST + c + 1] = tf32r(s[ni][1]);
            Ps[(rm + group + 8) * PS_ST + c    ] = tf32r(s[ni][2]);
            Ps[(rm + group + 8) * PS_ST + c + 1] = tf32r(s[ni][3]);
        }
        __syncwarp();
#pragma unroll
        for (int ks = 0; ks < 64; ks += 8) {
            uint32_t a[4];
            a[0] = __float_as_uint(Ps[(rm + group)     * PS_ST + ks + tig]);
            a[1] = __float_as_uint(Ps[(rm + group + 8) * PS_ST + ks + tig]);
            a[2] = __float_as_uint(Ps[(rm + group)     * PS_ST + ks + tig + 4]);
            a[3] = __float_as_uint(Ps[(rm + group + 8) * PS_ST + ks + tig + 4]);
#pragma unroll
            for (int ni = 0; ni < 8; ni++) {
                uint32_t bb[2];
                bb[0] = __float_as_uint(Vs[(ks + tig)     * VS_ST + ni * 8 + group]);
                bb[1] = __float_as_uint(Vs[(ks + tig + 4) * VS_ST + ni * 8 + group]);
                mma_tf32(o[ni], a, bb);
            }
        }
        __syncwarp();
    }

    float inv0 = 1.f / l0, inv1 = 1.f / l1;
    int r0 = qt0 + rm + group;
#pragma unroll
    for (int ni = 0; ni < 8; ni++) {
        int c = ni * 8 + 2 * tig;
        float2 w0 = make_float2(o[ni][0] * inv0, o[ni][1] * inv0);
        float2 w1 = make_float2(o[ni][2] * inv1, o[ni][3] * inv1);
        *(float2*)&out[(size_t)(b * SEQ + r0)     * DMODEL + h * 64 + c] = w0;
        *(float2*)&out[(size_t)(b * SEQ + r0 + 8) * DMODEL + h * 64 + c] = w1;
    }
}

// ---------------- swiglu elementwise (float4) --------------------------------
__global__ void swiglu_kernel(float4* __restrict__ u, const float4* __restrict__ v, int n4) {
    int i = blockIdx.x * blockDim.x + threadIdx.x;
    if (i < n4) {
        float4 a = u[i], b = v[i];
        a.x = a.x / (1.f + expf(-a.x)) * b.x;
        a.y = a.y / (1.f + expf(-a.y)) * b.y;
        a.z = a.z / (1.f + expf(-a.z)) * b.z;
        a.w = a.w / (1.f + expf(-a.w)) * b.w;
        u[i] = a;
    }
}

// ---------------- halt head --------------------------------------------------
__global__ void halt_kernel(const float* __restrict__ hh, const float* __restrict__ Wh2,
                            const float* __restrict__ bh2, const float* __restrict__ cum,
                            float* __restrict__ halt_out, float* __restrict__ cum_out) {
    int row = blockIdx.x;
    int t = threadIdx.x;
    float p = hh[(size_t)row * DHALT + t] * Wh2[t];
    for (int off = 16; off; off >>= 1) p += __shfl_xor_sync(0xffffffffu, p, off);
    __shared__ float red[8];
    if ((t & 31) == 0) red[t >> 5] = p;
    __syncthreads();
    if (t == 0) {
        float sum = red[0] + red[1] + red[2] + red[3] + red[4] + red[5] + red[6] + red[7] + bh2[0];
        float hp = 1.f / (1.f + expf(-sum));
        float c = cum[row];
        float still = (c < 0.99f) ? 1.f : 0.f;
        halt_out[row] = hp;
        cum_out[row] = c + hp * still;
    }
}

// ---------------- launch ------------------------------------------------------
extern "C" void kernel_launch(void* const* d_in, const int* in_sizes, int n_in,
                              void* d_out, int out_size) {
    const float* x    = (const float*)d_in[0];
    const float* cum  = (const float*)d_in[1];
    const float* g1   = (const float*)d_in[2];
    const float* g2   = (const float*)d_in[3];
    const float* Wqkv = (const float*)d_in[4];
    const float* Wo   = (const float*)d_in[5];
    const float* W1   = (const float*)d_in[6];
    const float* W2   = (const float*)d_in[7];
    const float* W3   = (const float*)d_in[8];
    const float* Wh1  = (const float*)d_in[9];
    const float* bh1  = (const float*)d_in[10];
    const float* Wh2  = (const float*)d_in[11];
    const float* bh2  = (const float*)d_in[12];

    float* outx = (float*)d_out;
    float* outh = outx + (size_t)NROWS * DMODEL;
    float* outc = outh + NROWS;

    float *h1, *qkvb, *attnb, *x1, *h2, *u, *v, *hhp;
    cudaGetSymbolAddress((void**)&h1,   g_h1);
    cudaGetSymbolAddress((void**)&qkvb, g_qkv);
    cudaGetSymbolAddress((void**)&attnb,g_attn);
    cudaGetSymbolAddress((void**)&x1,   g_x1);
    cudaGetSymbolAddress((void**)&h2,   g_h2);
    cudaGetSymbolAddress((void**)&u,    g_u);
    cudaGetSymbolAddress((void**)&v,    g_v);
    cudaGetSymbolAddress((void**)&hhp,  g_hh);

    cudaFuncSetAttribute(gemm_tc<0,1,1>, cudaFuncAttributeMaxDynamicSharedMemorySize, GEMM_SMEM);
    cudaFuncSetAttribute(gemm_tc<1,1,1>, cudaFuncAttributeMaxDynamicSharedMemorySize, GEMM_SMEM);
    cudaFuncSetAttribute(gemm_tc<0,1,0>, cudaFuncAttributeMaxDynamicSharedMemorySize, GEMM_SMEM);
    cudaFuncSetAttribute(gemm_tc<1,0,1>, cudaFuncAttributeMaxDynamicSharedMemorySize, GEMM_SMEM);
    cudaFuncSetAttribute(gemm_tc<2,1,1>, cudaFuncAttributeMaxDynamicSharedMemorySize, GEMM_SMEM);
    cudaFuncSetAttribute(attn_tc, cudaFuncAttributeMaxDynamicSharedMemorySize, ATTN_SMEM);

    // 1. h1 = rmsnorm(x, g1)
    rmsnorm_kernel<<<NROWS, 256>>>(x, g1, h1);
    // 2. qkv = h1 @ Wqkv
    gemm_tc<0,1,1><<<dim3(3 * DMODEL / 128, NROWS / 128), 256, GEMM_SMEM>>>(
        h1, Wqkv, qkvb, nullptr, NROWS, DMODEL, 3 * DMODEL);
    // 3. attention (tf32 tensor cores)
    attn_tc<<<dim3(SEQ / 64, BATCH * NHEAD), 128, ATTN_SMEM>>>(qkvb, attnb);
    // 4. x1 = x + attn @ Wo
    gemm_tc<1,1,1><<<dim3(DMODEL / 128, NROWS / 128), 256, GEMM_SMEM>>>(
        attnb, Wo, x1, x, NROWS, DMODEL, DMODEL);
    // 5. h2 = rmsnorm(x1, g2)
    rmsnorm_kernel<<<NROWS, 256>>>(x1, g2, h2);
    // 6. u = h2 @ W1, v = h2 @ W2
    gemm_tc<0,1,0><<<dim3((DFF + 127) / 128, NROWS / 128), 256, GEMM_SMEM>>>(
        h2, W1, u, nullptr, NROWS, DMODEL, DFF);
    gemm_tc<0,1,0><<<dim3((DFF + 127) / 128, NROWS / 128), 256, GEMM_SMEM>>>(
        h2, W2, v, nullptr, NROWS, DMODEL, DFF);
    // 7. u = silu(u) * v
    {
        int n4 = NROWS * DFF / 4;
        swiglu_kernel<<<(n4 + 255) / 256, 256>>>((float4*)u, (const float4*)v, n4);
    }
    // 8. final x = x1 + u @ W3 -> d_out
    gemm_tc<1,0,1><<<dim3(DMODEL / 128, NROWS / 128), 256, GEMM_SMEM>>>(
        u, W3, outx, x1, NROWS, DFF, DMODEL);
    // 9. hh = gelu(x @ Wh1 + bh1)
    gemm_tc<2,1,1><<<dim3(DHALT / 128, NROWS / 128), 256, GEMM_SMEM>>>(
        outx, Wh1, hhp, bh1, NROWS, DMODEL, DHALT);
    // 10. halt probs + cum update
    halt_kernel<<<NROWS, 256>>>(hhp, Wh2, bh2, cum, outh, outc);
}

// round 10
// speedup vs baseline: 3.3166x; 1.0053x over previous
#include <cuda_runtime.h>
#include <math.h>
#include <stdint.h>

#define DMODEL 1024
#define NHEAD  16
#define HDIM   64
#define DFF    2730
#define DHALT  256
#define BATCH  2
#define SEQ    2048
#define NROWS  (BATCH*SEQ)   // 4096

// ---------------- scratch (static device globals: allocation-guard safe) ---------
__device__ float g_h1[(size_t)NROWS*DMODEL];
__device__ float g_qkv[(size_t)NROWS*3*DMODEL];
__device__ float g_attn[(size_t)NROWS*DMODEL];
__device__ float g_x1[(size_t)NROWS*DMODEL];
__device__ float g_h2[(size_t)NROWS*DMODEL];
__device__ float g_u[(size_t)NROWS*DFF];
__device__ float g_v[(size_t)NROWS*DFF];
__device__ float g_hh[(size_t)NROWS*DHALT];

// ---------------- rmsnorm: one block per row --------------------------------
__global__ void rmsnorm_kernel(const float* __restrict__ x, const float* __restrict__ g,
                               float* __restrict__ y) {
    int row = blockIdx.x;
    const float* xr = x + (size_t)row * DMODEL;
    int t = threadIdx.x;
    float v[4];
    float ss = 0.f;
#pragma unroll
    for (int i = 0; i < 4; i++) { v[i] = xr[t + i * 256]; ss += v[i] * v[i]; }
    for (int off = 16; off; off >>= 1) ss += __shfl_xor_sync(0xffffffffu, ss, off);
    __shared__ float red[8];
    if ((t & 31) == 0) red[t >> 5] = ss;
    __syncthreads();
    if (t < 8) {
        float s2 = red[t];
        for (int off = 4; off; off >>= 1) s2 += __shfl_xor_sync(0xffu, s2, off);
        if (t == 0) red[0] = s2;
    }
    __syncthreads();
    float inv = rsqrtf(red[0] * (1.0f / DMODEL) + 1e-6f);
    float* yr = y + (size_t)row * DMODEL;
#pragma unroll
    for (int i = 0; i < 4; i++) {
        int c = t + i * 256;
        yr[c] = v[i] * inv * g[c];
    }
}

// ---------------- async-copy + mma helpers -----------------------------------
__device__ __forceinline__ uint32_t s2u(const void* p) {
    return (uint32_t)__cvta_generic_to_shared(p);
}
__device__ __forceinline__ void cp16(uint32_t d, const void* s) {
    asm volatile("cp.async.cg.shared.global [%0], [%1], 16;" :: "r"(d), "l"(s));
}
__device__ __forceinline__ void cp4(uint32_t d, const void* s) {
    asm volatile("cp.async.ca.shared.global [%0], [%1], 4;" :: "r"(d), "l"(s));
}
__device__ __forceinline__ void cp_commit() {
    asm volatile("cp.async.commit_group;");
}
__device__ __forceinline__ void mma_tf32(float c[4], const uint32_t a[4], const uint32_t b[2]) {
    asm volatile(
        "mma.sync.aligned.m16n8k8.row.col.f32.tf32.tf32.f32 "
        "{%0,%1,%2,%3}, {%4,%5,%6,%7}, {%8,%9}, {%0,%1,%2,%3};"
        : "+f"(c[0]), "+f"(c[1]), "+f"(c[2]), "+f"(c[3])
        : "r"(a[0]), "r"(a[1]), "r"(a[2]), "r"(a[3]), "r"(b[0]), "r"(b[1]));
}
__device__ __forceinline__ float tf32r(float x) {   // round-to-nearest tf32
    uint32_t y;
    asm("cvt.rna.tf32.f32 %0, %1;" : "=r"(y) : "f"(x));
    return __uint_as_float(y);
}

// ---------------- TF32 tensor-core GEMM v4 -----------------------------------
// 128 threads = 4 warps (2x2), warp tile 64x64. Block tile 128x128, BK=32,
// 3-stage cp.async, 1 barrier/ktile. LDS/MMA = 1.0 (was 1.5).
#define AS_STRIDE 36
#define BS_STRIDE 136
#define A_TILE (128 * AS_STRIDE)
#define B_TILE (32 * BS_STRIDE)
#define STAGE  (A_TILE + B_TILE)
#define NSTAGE 3
#define GEMM_SMEM (NSTAGE * STAGE * sizeof(float))   // 107520 B

template <int MODE, int AVEC, int BVEC>
__global__ void __launch_bounds__(128) gemm_tc(const float* __restrict__ A,
                                               const float* __restrict__ Bm,
                                               float* __restrict__ C,
                                               const float* __restrict__ E,
                                               int M, int K, int N) {
    extern __shared__ float smem[];
    int tid = threadIdx.x;
    int w = tid >> 5, lane = tid & 31;
    int warpM = w >> 1, warpN = w & 1;          // 2 x 2 grid of 64x64 warp tiles
    int group = lane >> 2, tig = lane & 3;
    int m0 = blockIdx.y * 128, n0 = blockIdx.x * 128;

    auto load_tile = [&](int k0, int stg) {
        float* sA = smem + stg * STAGE;
        float* sB = sA + A_TILE;
        if (AVEC) {
#pragma unroll
            for (int i = 0; i < 8; i++) {            // A: 128x32, 8 x 16B per thread
                int c = i * 128 + tid;
                int m = c >> 3, k4 = (c & 7) * 4;
                float* dp = sA + m * AS_STRIDE + k4;
                const float* sp = A + (size_t)(m0 + m) * K + k0 + k4;
                if (k0 + k4 + 4 <= K) cp16(s2u(dp), sp);
                else {
#pragma unroll
                    for (int e = 0; e < 4; e++) dp[e] = (k0 + k4 + e < K) ? sp[e] : 0.f;
                }
            }
        } else {
#pragma unroll
            for (int i = 0; i < 32; i++) {           // A: 4B path (ragged K)
                int c = i * 128 + tid;
                int m = c >> 5, kk = c & 31;
                float* dp = sA + m * AS_STRIDE + kk;
                if (k0 + kk < K) cp4(s2u(dp), A + (size_t)(m0 + m) * K + k0 + kk);
                else *dp = 0.f;
            }
        }
        if (BVEC) {
#pragma unroll
            for (int i = 0; i < 8; i++) {            // B: 32x128, 8 x 16B per thread
                int c = i * 128 + tid;
                int kk = c >> 5, n4 = (c & 31) * 4;
                float* dp = sB + kk * BS_STRIDE + n4;
                if (k0 + kk < K) cp16(s2u(dp), Bm + (size_t)(k0 + kk) * N + n0 + n4);
                else { dp[0] = 0.f; dp[1] = 0.f; dp[2] = 0.f; dp[3] = 0.f; }
            }
        } else {
#pragma unroll
            for (int i = 0; i < 32; i++) {           // B: 4B path (ragged N)
                int c = i * 128 + tid;
                int kk = c >> 7, n = c & 127;
                float* dp = sB + kk * BS_STRIDE + n;
                if (k0 + kk < K && n0 + n < N) cp4(s2u(dp), Bm + (size_t)(k0 + kk) * N + n0 + n);
                else *dp = 0.f;
            }
        }
    };

    float acc[4][8][4];
#pragma unroll
    for (int mi = 0; mi < 4; mi++)
#pragma unroll
        for (int ni = 0; ni < 8; ni++)
#pragma unroll
            for (int r = 0; r < 4; r++) acc[mi][ni][r] = 0.f;

    int ntiles = (K + 31) / 32;
    load_tile(0, 0);
    cp_commit();
    if (ntiles > 1) { load_tile(32, 1); cp_commit(); }

    for (int t = 0; t < ntiles; t++) {
        if (t + 1 < ntiles) asm volatile("cp.async.wait_group 1;");
        else                asm volatile("cp.async.wait_group 0;");
        __syncthreads();   // single barrier per ktile (3-stage: buf t+2 != t, t+1)
        if (t + 2 < ntiles) {
            load_tile((t + 2) * 32, (t + 2) % NSTAGE);
            cp_commit();
        }

        const float* sA = smem + (t % NSTAGE) * STAGE;
        const float* sB = sA + A_TILE;
#pragma unroll
        for (int ks = 0; ks < 32; ks += 8) {
            uint32_t afrag[4][4], bfrag[8][2];
#pragma unroll
            for (int mi = 0; mi < 4; mi++) {
                int rm = warpM * 64 + mi * 16;
                afrag[mi][0] = __float_as_uint(sA[(rm + group)     * AS_STRIDE + ks + tig]);
                afrag[mi][1] = __float_as_uint(sA[(rm + group + 8) * AS_STRIDE + ks + tig]);
                afrag[mi][2] = __float_as_uint(sA[(rm + group)     * AS_STRIDE + ks + tig + 4]);
                afrag[mi][3] = __float_as_uint(sA[(rm + group + 8) * AS_STRIDE + ks + tig + 4]);
            }
#pragma unroll
            for (int ni = 0; ni < 8; ni++) {
                int cn = warpN * 64 + ni * 8;
                bfrag[ni][0] = __float_as_uint(sB[(ks + tig)     * BS_STRIDE + cn + group]);
                bfrag[ni][1] = __float_as_uint(sB[(ks + tig + 4) * BS_STRIDE + cn + group]);
            }
#pragma unroll
            for (int mi = 0; mi < 4; mi++)
#pragma unroll
                for (int ni = 0; ni < 8; ni++)
                    mma_tf32(acc[mi][ni], afrag[mi], bfrag[ni]);
        }
    }

    // epilogue: (c0,c1) = cols (c,c+1) @ row; (c2,c3) same cols @ row+8.
#pragma unroll
    for (int mi = 0; mi < 4; mi++) {
        int row = m0 + warpM * 64 + mi * 16 + group;
#pragma unroll
        for (int ni = 0; ni < 8; ni++) {
            int col = n0 + warpN * 64 + ni * 8 + tig * 2;
            if (col >= N) continue;
            float2 lo = make_float2(acc[mi][ni][0], acc[mi][ni][1]);
            float2 hi = make_float2(acc[mi][ni][2], acc[mi][ni][3]);
            if (MODE == 1) {
                float2 e0 = *(const float2*)&E[(size_t)row * N + col];
                float2 e1 = *(const float2*)&E[(size_t)(row + 8) * N + col];
                lo.x += e0.x; lo.y += e0.y; hi.x += e1.x; hi.y += e1.y;
            }
            if (MODE == 2) {
                float2 bb = *(const float2*)&E[col];
                lo.x += bb.x; lo.y += bb.y; hi.x += bb.x; hi.y += bb.y;
                lo.x = 0.5f * lo.x * (1.f + erff(lo.x * 0.70710678118654752f));
                lo.y = 0.5f * lo.y * (1.f + erff(lo.y * 0.70710678118654752f));
                hi.x = 0.5f * hi.x * (1.f + erff(hi.x * 0.70710678118654752f));
                hi.y = 0.5f * hi.y * (1.f + erff(hi.y * 0.70710678118654752f));
            }
            *(float2*)&C[(size_t)row * N + col] = lo;
            *(float2*)&C[(size_t)(row + 8) * N + col] = hi;
        }
    }
}

// ---------------- tf32 tensor-core flash attention (unchanged, passing) ------
#define QS_ST 68
#define KT_ST 72
#define VS_ST 72
#define PS_ST 68
#define ATTN_SMEM ((64*QS_ST + 64*KT_ST + 64*VS_ST + 64*PS_ST) * 4)  // 71680 B

__global__ void __launch_bounds__(128) attn_tc(const float* __restrict__ qkv,
                                               float* __restrict__ out) {
    extern __shared__ float sm[];
    float* Qs = sm;
    float* KT = Qs + 64 * QS_ST;
    float* Vs = KT + 64 * KT_ST;
    float* Ps = Vs + 64 * VS_ST;
    int tid = threadIdx.x;
    int warp = tid >> 5, lane = tid & 31;
    int group = lane >> 2, tig = lane & 3;
    int bh = blockIdx.y;
    int b = bh >> 4, h = bh & 15;
    int qt0 = blockIdx.x * 64;
    size_t base = (size_t)b * SEQ * 3072;
    int rm = warp * 16;

#pragma unroll
    for (int i = 0; i < 8; i++) {
        int e = i * 128 + tid;
        int r = e >> 4, dq = e & 15;
        float4 q = *(const float4*)&qkv[base + (size_t)(qt0 + r) * 3072 + h * 64 + dq * 4];
        float* d = &Qs[r * QS_ST + dq * 4];
        d[0] = tf32r(q.x); d[1] = tf32r(q.y); d[2] = tf32r(q.z); d[3] = tf32r(q.w);
    }

    float o[8][4];
    float m0 = -1e30f, m1 = -1e30f, l0 = 0.f, l1 = 0.f;
#pragma unroll
    for (int ni = 0; ni < 8; ni++)
#pragma unroll
        for (int r = 0; r < 4; r++) o[ni][r] = 0.f;

    int jt_max = blockIdx.x;
    for (int jt = 0; jt <= jt_max; jt++) {
        int j0 = jt * 64;
        __syncthreads();
#pragma unroll
        for (int i = 0; i < 8; i++) {
            int e = i * 128 + tid;
            int r = e >> 4, dq = e & 15;
            float4 k4 = *(const float4*)&qkv[base + (size_t)(j0 + r) * 3072 + 1024 + h * 64 + dq * 4];
            KT[(dq * 4 + 0) * KT_ST + r] = tf32r(k4.x);
            KT[(dq * 4 + 1) * KT_ST + r] = tf32r(k4.y);
            KT[(dq * 4 + 2) * KT_ST + r] = tf32r(k4.z);
            KT[(dq * 4 + 3) * KT_ST + r] = tf32r(k4.w);
            float4 v4 = *(const float4*)&qkv[base + (size_t)(j0 + r) * 3072 + 2048 + h * 64 + dq * 4];
            float4 vt;
            vt.x = tf32r(v4.x); vt.y = tf32r(v4.y); vt.z = tf32r(v4.z); vt.w = tf32r(v4.w);
            *(float4*)&Vs[r * VS_ST + dq * 4] = vt;
        }
        __syncthreads();

        float s[8][4];
#pragma unroll
        for (int ni = 0; ni < 8; ni++)
#pragma unroll
            for (int r = 0; r < 4; r++) s[ni][r] = 0.f;
#pragma unroll
        for (int ks = 0; ks < 64; ks += 8) {
            uint32_t a[4];
            a[0] = __float_as_uint(Qs[(rm + group)     * QS_ST + ks + tig]);
            a[1] = __float_as_uint(Qs[(rm + group + 8) * QS_ST + ks + tig]);
            a[2] = __float_as_uint(Qs[(rm + group)     * QS_ST + ks + tig + 4]);
            a[3] = __float_as_uint(Qs[(rm + group + 8) * QS_ST + ks + tig + 4]);
#pragma unroll
            for (int ni = 0; ni < 8; ni++) {
                uint32_t bb[2];
                bb[0] = __float_as_uint(KT[(ks + tig)     * KT_ST + ni * 8 + group]);
                bb[1] = __float_as_uint(KT[(ks + tig + 4) * KT_ST + ni * 8 + group]);
                mma_tf32(s[ni], a, bb);
            }
        }
        int row0 = qt0 + rm + group;
        bool diag = (jt == jt_max);
#pragma unroll
        for (int ni = 0; ni < 8; ni++) {
#pragma unroll
            for (int r = 0; r < 4; r++) s[ni][r] *= 0.125f;
            if (diag) {
                int c0 = j0 + ni * 8 + 2 * tig;
                if (c0     > row0)     s[ni][0] = -1e30f;
                if (c0 + 1 > row0)     s[ni][1] = -1e30f;
                if (c0     > row0 + 8) s[ni][2] = -1e30f;
                if (c0 + 1 > row0 + 8) s[ni][3] = -1e30f;
            }
        }
        float tm0 = -1e30f, tm1 = -1e30f;
#pragma unroll
        for (int ni = 0; ni < 8; ni++) {
            tm0 = fmaxf(tm0, fmaxf(s[ni][0], s[ni][1]));
            tm1 = fmaxf(tm1, fmaxf(s[ni][2], s[ni][3]));
        }
        tm0 = fmaxf(tm0, __shfl_xor_sync(0xffffffffu, tm0, 1));
        tm0 = fmaxf(tm0, __shfl_xor_sync(0xffffffffu, tm0, 2));
        tm1 = fmaxf(tm1, __shfl_xor_sync(0xffffffffu, tm1, 1));
        tm1 = fmaxf(tm1, __shfl_xor_sync(0xffffffffu, tm1, 2));
        float nm0 = fmaxf(m0, tm0), nm1 = fmaxf(m1, tm1);
        float f0 = __expf(m0 - nm0), f1 = __expf(m1 - nm1);
        float rs0 = 0.f, rs1 = 0.f;
#pragma unroll
        for (int ni = 0; ni < 8; ni++) {
            s[ni][0] = __expf(s[ni][0] - nm0);
            s[ni][1] = __expf(s[ni][1] - nm0);
            s[ni][2] = __expf(s[ni][2] - nm1);
            s[ni][3] = __expf(s[ni][3] - nm1);
            rs0 += s[ni][0] + s[ni][1];
            rs1 += s[ni][2] + s[ni][3];
        }
        rs0 += __shfl_xor_sync(0xffffffffu, rs0, 1);
        rs0 += __shfl_xor_sync(0xffffffffu, rs0, 2);
        rs1 += __shfl_xor_sync(0xffffffffu, rs1, 1);
        rs1 += __shfl_xor_sync(0xffffffffu, rs1, 2);
        l0 = l0 * f0 + rs0; l1 = l1 * f1 + rs1;
        m0 = nm0; m1 = nm1;
#pragma unroll
        for (int ni = 0; ni < 8; ni++) {
            o[ni][0] *= f0; o[ni][1] *= f0; o[ni][2] *= f1; o[ni][3] *= f1;
        }
#pragma unroll
        for (int ni = 0; ni < 8; ni++) {
            int c = ni * 8 + 2 * tig;
            Ps[(rm + group)     * PS_ST + c    ] = tf32r(s[ni][0]);
            Ps[(rm + group)     * PS_ST + c + 1] = tf32r(s[ni][1]);
            Ps[(rm + group + 8) * PS_ST + c    ] = tf32r(s[ni][2]);
            Ps[(rm + group + 8) * PS_ST + c + 1] = tf32r(s[ni][3]);
        }
        __syncwarp();
#pragma unroll
        for (int ks = 0; ks < 64; ks += 8) {
            uint32_t a[4];
            a[0] = __float_as_uint(Ps[(rm + group)     * PS_ST + ks + tig]);
            a[1] = __float_as_uint(Ps[(rm + group + 8) * PS_ST + ks + tig]);
            a[2] = __float_as_uint(Ps[(rm + group)     * PS_ST + ks + tig + 4]);
            a[3] = __float_as_uint(Ps[(rm + group + 8) * PS_ST + ks + tig + 4]);
#pragma unroll
            for (int ni = 0; ni < 8; ni++) {
                uint32_t bb[2];
                bb[0] = __float_as_uint(Vs[(ks + tig)     * VS_ST + ni * 8 + group]);
                bb[1] = __float_as_uint(Vs[(ks + tig + 4) * VS_ST + ni * 8 + group]);
                mma_tf32(o[ni], a, bb);
            }
        }
        __syncwarp();
    }

    float inv0 = 1.f / l0, inv1 = 1.f / l1;
    int r0 = qt0 + rm + group;
#pragma unroll
    for (int ni = 0; ni < 8; ni++) {
        int c = ni * 8 + 2 * tig;
        float2 w0 = make_float2(o[ni][0] * inv0, o[ni][1] * inv0);
        float2 w1 = make_float2(o[ni][2] * inv1, o[ni][3] * inv1);
        *(float2*)&out[(size_t)(b * SEQ + r0)     * DMODEL + h * 64 + c] = w0;
        *(float2*)&out[(size_t)(b * SEQ + r0 + 8) * DMODEL + h * 64 + c] = w1;
    }
}

// ---------------- swiglu elementwise (float4) --------------------------------
__global__ void swiglu_kernel(float4* __restrict__ u, const float4* __restrict__ v, int n4) {
    int i = blockIdx.x * blockDim.x + threadIdx.x;
    if (i < n4) {
        float4 a = u[i], b = v[i];
        a.x = a.x / (1.f + expf(-a.x)) * b.x;
        a.y = a.y / (1.f + expf(-a.y)) * b.y;
        a.z = a.z / (1.f + expf(-a.z)) * b.z;
        a.w = a.w / (1.f + expf(-a.w)) * b.w;
        u[i] = a;
    }
}

// ---------------- halt head --------------------------------------------------
__global__ void halt_kernel(const float* __restrict__ hh, const float* __restrict__ Wh2,
                            const float* __restrict__ bh2, const float* __restrict__ cum,
                            float* __restrict__ halt_out, float* __restrict__ cum_out) {
    int row = blockIdx.x;
    int t = threadIdx.x;
    float p = hh[(size_t)row * DHALT + t] * Wh2[t];
    for (int off = 16; off; off >>= 1) p += __shfl_xor_sync(0xffffffffu, p, off);
    __shared__ float red[8];
    if ((t & 31) == 0) red[t >> 5] = p;
    __syncthreads();
    if (t == 0) {
        float sum = red[0] + red[1] + red[2] + red[3] + red[4] + red[5] + red[6] + red[7] + bh2[0];
        float hp = 1.f / (1.f + expf(-sum));
        float c = cum[row];
        float still = (c < 0.99f) ? 1.f : 0.f;
        halt_out[row] = hp;
        cum_out[row] = c + hp * still;
    }
}

// ---------------- launch ------------------------------------------------------
extern "C" void kernel_launch(void* const* d_in, const int* in_sizes, int n_in,
                              void* d_out, int out_size) {
    const float* x    = (const float*)d_in[0];
    const float* cum  = (const float*)d_in[1];
    const float* g1   = (const float*)d_in[2];
    const float* g2   = (const float*)d_in[3];
    const float* Wqkv = (const float*)d_in[4];
    const float* Wo   = (const float*)d_in[5];
    const float* W1   = (const float*)d_in[6];
    const float* W2   = (const float*)d_in[7];
    const float* W3   = (const float*)d_in[8];
    const float* Wh1  = (const float*)d_in[9];
    const float* bh1  = (const float*)d_in[10];
    const float* Wh2  = (const float*)d_in[11];
    const float* bh2  = (const float*)d_in[12];

    float* outx = (float*)d_out;
    float* outh = outx + (size_t)NROWS * DMODEL;
    float* outc = outh + NROWS;

    float *h1, *qkvb, *attnb, *x1, *h2, *u, *v, *hhp;
    cudaGetSymbolAddress((void**)&h1,   g_h1);
    cudaGetSymbolAddress((void**)&qkvb, g_qkv);
    cudaGetSymbolAddress((void**)&attnb,g_attn);
    cudaGetSymbolAddress((void**)&x1,   g_x1);
    cudaGetSymbolAddress((void**)&h2,   g_h2);
    cudaGetSymbolAddress((void**)&u,    g_u);
    cudaGetSymbolAddress((void**)&v,    g_v);
    cudaGetSymbolAddress((void**)&hhp,  g_hh);

    cudaFuncSetAttribute(gemm_tc<0,1,1>, cudaFuncAttributeMaxDynamicSharedMemorySize, GEMM_SMEM);
    cudaFuncSetAttribute(gemm_tc<1,1,1>, cudaFuncAttributeMaxDynamicSharedMemorySize, GEMM_SMEM);
    cudaFuncSetAttribute(gemm_tc<0,1,0>, cudaFuncAttributeMaxDynamicSharedMemorySize, GEMM_SMEM);
    cudaFuncSetAttribute(gemm_tc<1,0,1>, cudaFuncAttributeMaxDynamicSharedMemorySize, GEMM_SMEM);
    cudaFuncSetAttribute(gemm_tc<2,1,1>, cudaFuncAttributeMaxDynamicSharedMemorySize, GEMM_SMEM);
    cudaFuncSetAttribute(attn_tc, cudaFuncAttributeMaxDynamicSharedMemorySize, ATTN_SMEM);

    // 1. h1 = rmsnorm(x, g1)
    rmsnorm_kernel<<<NROWS, 256>>>(x, g1, h1);
    // 2. qkv = h1 @ Wqkv
    gemm_tc<0,1,1><<<dim3(3 * DMODEL / 128, NROWS / 128), 128, GEMM_SMEM>>>(
        h1, Wqkv, qkvb, nullptr, NROWS, DMODEL, 3 * DMODEL);
    // 3. attention (tf32 tensor cores)
    attn_tc<<<dim3(SEQ / 64, BATCH * NHEAD), 128, ATTN_SMEM>>>(qkvb, attnb);
    // 4. x1 = x + attn @ Wo
    gemm_tc<1,1,1><<<dim3(DMODEL / 128, NROWS / 128), 128, GEMM_SMEM>>>(
        attnb, Wo, x1, x, NROWS, DMODEL, DMODEL);
    // 5. h2 = rmsnorm(x1, g2)
    rmsnorm_kernel<<<NROWS, 256>>>(x1, g2, h2);
    // 6. u = h2 @ W1, v = h2 @ W2
    gemm_tc<0,1,0><<<dim3((DFF + 127) / 128, NROWS / 128), 128, GEMM_SMEM>>>(
        h2, W1, u, nullptr, NROWS, DMODEL, DFF);
    gemm_tc<0,1,0><<<dim3((DFF + 127) / 128, NROWS / 128), 128, GEMM_SMEM>>>(
        h2, W2, v, nullptr, NROWS, DMODEL, DFF);
    // 7. u = silu(u) * v
    {
        int n4 = NROWS * DFF / 4;
        swiglu_kernel<<<(n4 + 255) / 256, 256>>>((float4*)u, (const float4*)v, n4);
    }
    // 8. final x = x1 + u @ W3 -> d_out
    gemm_tc<1,0,1><<<dim3(DMODEL / 128, NROWS / 128), 128, GEMM_SMEM>>>(
        u, W3, outx, x1, NROWS, DFF, DMODEL);
    // 9. hh = gelu(x @ Wh1 + bh1)
    gemm_tc<2,1,1><<<dim3(DHALT / 128, NROWS / 128), 128, GEMM_SMEM>>>(
        outx, Wh1, hhp, bh1, NROWS, DMODEL, DHALT);
    // 10. halt probs + cum update
    halt_kernel<<<NROWS, 256>>>(hhp, Wh2, bh2, cum, outh, outc);
}

// round 11
// speedup vs baseline: 3.3316x; 1.0045x over previous
#include <cuda_runtime.h>
#include <math.h>
#include <stdint.h>

#define DMODEL 1024
#define NHEAD  16
#define HDIM   64
#define DFF    2730
#define DHALT  256
#define BATCH  2
#define SEQ    2048
#define NROWS  (BATCH*SEQ)   // 4096

// ---------------- scratch (static device globals: allocation-guard safe) ---------
__device__ float g_h1[(size_t)NROWS*DMODEL];
__device__ float g_qkv[(size_t)NROWS*3*DMODEL];
__device__ float g_attn[(size_t)NROWS*DMODEL];
__device__ float g_x1[(size_t)NROWS*DMODEL];
__device__ float g_h2[(size_t)NROWS*DMODEL];
__device__ float g_u[(size_t)NROWS*DFF];
__device__ float g_v[(size_t)NROWS*DFF];
__device__ float g_hh[(size_t)NROWS*DHALT];

// ---------------- rmsnorm: one block per row --------------------------------
__global__ void rmsnorm_kernel(const float* __restrict__ x, const float* __restrict__ g,
                               float* __restrict__ y) {
    int row = blockIdx.x;
    const float* xr = x + (size_t)row * DMODEL;
    int t = threadIdx.x;
    float v[4];
    float ss = 0.f;
#pragma unroll
    for (int i = 0; i < 4; i++) { v[i] = xr[t + i * 256]; ss += v[i] * v[i]; }
    for (int off = 16; off; off >>= 1) ss += __shfl_xor_sync(0xffffffffu, ss, off);
    __shared__ float red[8];
    if ((t & 31) == 0) red[t >> 5] = ss;
    __syncthreads();
    if (t < 8) {
        float s2 = red[t];
        for (int off = 4; off; off >>= 1) s2 += __shfl_xor_sync(0xffu, s2, off);
        if (t == 0) red[0] = s2;
    }
    __syncthreads();
    float inv = rsqrtf(red[0] * (1.0f / DMODEL) + 1e-6f);
    float* yr = y + (size_t)row * DMODEL;
#pragma unroll
    for (int i = 0; i < 4; i++) {
        int c = t + i * 256;
        yr[c] = v[i] * inv * g[c];
    }
}

// ---------------- async-copy + mma helpers -----------------------------------
__device__ __forceinline__ uint32_t s2u(const void* p) {
    return (uint32_t)__cvta_generic_to_shared(p);
}
__device__ __forceinline__ void cp16(uint32_t d, const void* s) {
    asm volatile("cp.async.cg.shared.global [%0], [%1], 16;" :: "r"(d), "l"(s));
}
__device__ __forceinline__ void cp4(uint32_t d, const void* s) {
    asm volatile("cp.async.ca.shared.global [%0], [%1], 4;" :: "r"(d), "l"(s));
}
__device__ __forceinline__ void cp_commit() {
    asm volatile("cp.async.commit_group;");
}
__device__ __forceinline__ void mma_tf32(float c[4], const uint32_t a[4], const uint32_t b[2]) {
    asm volatile(
        "mma.sync.aligned.m16n8k8.row.col.f32.tf32.tf32.f32 "
        "{%0,%1,%2,%3}, {%4,%5,%6,%7}, {%8,%9}, {%0,%1,%2,%3};"
        : "+f"(c[0]), "+f"(c[1]), "+f"(c[2]), "+f"(c[3])
        : "r"(a[0]), "r"(a[1]), "r"(a[2]), "r"(a[3]), "r"(b[0]), "r"(b[1]));
}
__device__ __forceinline__ float tf32r(float x) {   // round-to-nearest tf32
    uint32_t y;
    asm("cvt.rna.tf32.f32 %0, %1;" : "=r"(y) : "f"(x));
    return __uint_as_float(y);
}

// ---------------- TF32 tensor-core GEMM (R9 config: measured best) -----------
// 256 threads = 8 warps (2x4), warp tile 64x32. Block 128x128, BK=32,
// 3-stage cp.async, 1 barrier/ktile.
#define AS_STRIDE 36
#define BS_STRIDE 136
#define A_TILE (128 * AS_STRIDE)
#define B_TILE (32 * BS_STRIDE)
#define STAGE  (A_TILE + B_TILE)
#define NSTAGE 3
#define GEMM_SMEM (NSTAGE * STAGE * sizeof(float))   // 107520 B

template <int MODE, int AVEC, int BVEC>
__global__ void __launch_bounds__(256) gemm_tc(const float* __restrict__ A,
                                               const float* __restrict__ Bm,
                                               float* __restrict__ C,
                                               const float* __restrict__ E,
                                               int M, int K, int N) {
    extern __shared__ float smem[];
    int tid = threadIdx.x;
    int w = tid >> 5, lane = tid & 31;
    int warpM = w >> 2, warpN = w & 3;
    int group = lane >> 2, tig = lane & 3;
    int m0 = blockIdx.y * 128, n0 = blockIdx.x * 128;

    auto load_tile = [&](int k0, int stg) {
        float* sA = smem + stg * STAGE;
        float* sB = sA + A_TILE;
        if (AVEC) {
#pragma unroll
            for (int i = 0; i < 4; i++) {
                int c = i * 256 + tid;
                int m = c >> 3, k4 = (c & 7) * 4;
                float* dp = sA + m * AS_STRIDE + k4;
                const float* sp = A + (size_t)(m0 + m) * K + k0 + k4;
                if (k0 + k4 + 4 <= K) cp16(s2u(dp), sp);
                else {
#pragma unroll
                    for (int e = 0; e < 4; e++) dp[e] = (k0 + k4 + e < K) ? sp[e] : 0.f;
                }
            }
        } else {
#pragma unroll
            for (int i = 0; i < 16; i++) {
                int c = i * 256 + tid;
                int m = c >> 5, kk = c & 31;
                float* dp = sA + m * AS_STRIDE + kk;
                if (k0 + kk < K) cp4(s2u(dp), A + (size_t)(m0 + m) * K + k0 + kk);
                else *dp = 0.f;
            }
        }
        if (BVEC) {
#pragma unroll
            for (int i = 0; i < 4; i++) {
                int c = i * 256 + tid;
                int kk = c >> 5, n4 = (c & 31) * 4;
                float* dp = sB + kk * BS_STRIDE + n4;
                if (k0 + kk < K) cp16(s2u(dp), Bm + (size_t)(k0 + kk) * N + n0 + n4);
                else { dp[0] = 0.f; dp[1] = 0.f; dp[2] = 0.f; dp[3] = 0.f; }
            }
        } else {
#pragma unroll
            for (int i = 0; i < 16; i++) {
                int c = i * 256 + tid;
                int kk = c >> 7, n = c & 127;
                float* dp = sB + kk * BS_STRIDE + n;
                if (k0 + kk < K && n0 + n < N) cp4(s2u(dp), Bm + (size_t)(k0 + kk) * N + n0 + n);
                else *dp = 0.f;
            }
        }
    };

    float acc[4][4][4];
#pragma unroll
    for (int mi = 0; mi < 4; mi++)
#pragma unroll
        for (int ni = 0; ni < 4; ni++)
#pragma unroll
            for (int r = 0; r < 4; r++) acc[mi][ni][r] = 0.f;

    int ntiles = (K + 31) / 32;
    load_tile(0, 0);
    cp_commit();
    if (ntiles > 1) { load_tile(32, 1); cp_commit(); }

    for (int t = 0; t < ntiles; t++) {
        if (t + 1 < ntiles) asm volatile("cp.async.wait_group 1;");
        else                asm volatile("cp.async.wait_group 0;");
        __syncthreads();
        if (t + 2 < ntiles) {
            load_tile((t + 2) * 32, (t + 2) % NSTAGE);
            cp_commit();
        }

        const float* sA = smem + (t % NSTAGE) * STAGE;
        const float* sB = sA + A_TILE;
#pragma unroll
        for (int ks = 0; ks < 32; ks += 8) {
            uint32_t afrag[4][4], bfrag[4][2];
#pragma unroll
            for (int mi = 0; mi < 4; mi++) {
                int rm = warpM * 64 + mi * 16;
                afrag[mi][0] = __float_as_uint(sA[(rm + group)     * AS_STRIDE + ks + tig]);
                afrag[mi][1] = __float_as_uint(sA[(rm + group + 8) * AS_STRIDE + ks + tig]);
                afrag[mi][2] = __float_as_uint(sA[(rm + group)     * AS_STRIDE + ks + tig + 4]);
                afrag[mi][3] = __float_as_uint(sA[(rm + group + 8) * AS_STRIDE + ks + tig + 4]);
            }
#pragma unroll
            for (int ni = 0; ni < 4; ni++) {
                int cn = warpN * 32 + ni * 8;
                bfrag[ni][0] = __float_as_uint(sB[(ks + tig)     * BS_STRIDE + cn + group]);
                bfrag[ni][1] = __float_as_uint(sB[(ks + tig + 4) * BS_STRIDE + cn + group]);
            }
#pragma unroll
            for (int mi = 0; mi < 4; mi++)
#pragma unroll
                for (int ni = 0; ni < 4; ni++)
                    mma_tf32(acc[mi][ni], afrag[mi], bfrag[ni]);
        }
    }

#pragma unroll
    for (int mi = 0; mi < 4; mi++) {
        int row = m0 + warpM * 64 + mi * 16 + group;
#pragma unroll
        for (int ni = 0; ni < 4; ni++) {
            int col = n0 + warpN * 32 + ni * 8 + tig * 2;
            if (col >= N) continue;
            float2 lo = make_float2(acc[mi][ni][0], acc[mi][ni][1]);
            float2 hi = make_float2(acc[mi][ni][2], acc[mi][ni][3]);
            if (MODE == 1) {
                float2 e0 = *(const float2*)&E[(size_t)row * N + col];
                float2 e1 = *(const float2*)&E[(size_t)(row + 8) * N + col];
                lo.x += e0.x; lo.y += e0.y; hi.x += e1.x; hi.y += e1.y;
            }
            if (MODE == 2) {
                float2 bb = *(const float2*)&E[col];
                lo.x += bb.x; lo.y += bb.y; hi.x += bb.x; hi.y += bb.y;
                lo.x = 0.5f * lo.x * (1.f + erff(lo.x * 0.70710678118654752f));
                lo.y = 0.5f * lo.y * (1.f + erff(lo.y * 0.70710678118654752f));
                hi.x = 0.5f * hi.x * (1.f + erff(hi.x * 0.70710678118654752f));
                hi.y = 0.5f * hi.y * (1.f + erff(hi.y * 0.70710678118654752f));
            }
            *(float2*)&C[(size_t)row * N + col] = lo;
            *(float2*)&C[(size_t)(row + 8) * N + col] = hi;
        }
    }
}

// ---------------- tf32 flash attention with register-staged KV prefetch ------
#define QS_ST 68
#define KT_ST 72
#define VS_ST 72
#define PS_ST 68
#define ATTN_SMEM ((64*QS_ST + 64*KT_ST + 64*VS_ST + 64*PS_ST) * 4)  // 71680 B

__global__ void __launch_bounds__(128) attn_tc(const float* __restrict__ qkv,
                                               float* __restrict__ out) {
    extern __shared__ float sm[];
    float* Qs = sm;
    float* KT = Qs + 64 * QS_ST;
    float* Vs = KT + 64 * KT_ST;
    float* Ps = Vs + 64 * VS_ST;
    int tid = threadIdx.x;
    int warp = tid >> 5, lane = tid & 31;
    int group = lane >> 2, tig = lane & 3;
    int bh = blockIdx.y;
    int b = bh >> 4, h = bh & 15;
    int qt0 = blockIdx.x * 64;
    size_t base = (size_t)b * SEQ * 3072;
    int rm = warp * 16;
    // this thread's fixed (row, dq) for KV staging: covers 64x64 via 8 steps
    int ld_r = tid >> 4, ld_dq = tid & 15;      // r in [0,8), dq in [0,16)

    // load Q tile (rna-rounded)
#pragma unroll
    for (int i = 0; i < 8; i++) {
        int e = i * 128 + tid;
        int r = e >> 4, dq = e & 15;
        float4 q = *(const float4*)&qkv[base + (size_t)(qt0 + r) * 3072 + h * 64 + dq * 4];
        float* d = &Qs[r * QS_ST + dq * 4];
        d[0] = tf32r(q.x); d[1] = tf32r(q.y); d[2] = tf32r(q.z); d[3] = tf32r(q.w);
    }

    float4 kreg[8], vreg[8];
    auto load_kv = [&](int j0) {
#pragma unroll
        for (int i = 0; i < 8; i++) {
            int r = ld_r + i * 8;
            const float* kp = &qkv[base + (size_t)(j0 + r) * 3072 + 1024 + h * 64 + ld_dq * 4];
            kreg[i] = *(const float4*)kp;
            vreg[i] = *(const float4*)(kp + 1024);
        }
    };

    float o[8][4];
    float m0 = -1e30f, m1 = -1e30f, l0 = 0.f, l1 = 0.f;
#pragma unroll
    for (int ni = 0; ni < 8; ni++)
#pragma unroll
        for (int r = 0; r < 4; r++) o[ni][r] = 0.f;

    int jt_max = blockIdx.x;
    load_kv(0);                      // prefetch tile 0
    for (int jt = 0; jt <= jt_max; jt++) {
        __syncthreads();             // prior tile's KT/Vs (and Ps) reads complete
        // dump staged regs -> smem with tf32 rounding
#pragma unroll
        for (int i = 0; i < 8; i++) {
            int r = ld_r + i * 8;
            KT[(ld_dq * 4 + 0) * KT_ST + r] = tf32r(kreg[i].x);
            KT[(ld_dq * 4 + 1) * KT_ST + r] = tf32r(kreg[i].y);
            KT[(ld_dq * 4 + 2) * KT_ST + r] = tf32r(kreg[i].z);
            KT[(ld_dq * 4 + 3) * KT_ST + r] = tf32r(kreg[i].w);
            float4 vt;
            vt.x = tf32r(vreg[i].x); vt.y = tf32r(vreg[i].y);
            vt.z = tf32r(vreg[i].z); vt.w = tf32r(vreg[i].w);
            *(float4*)&Vs[r * VS_ST + ld_dq * 4] = vt;
        }
        __syncthreads();
        if (jt < jt_max) load_kv((jt + 1) * 64);   // LDGs overlap compute below

        int j0 = jt * 64;
        // ---- S = Q K^T ----
        float s[8][4];
#pragma unroll
        for (int ni = 0; ni < 8; ni++)
#pragma unroll
            for (int r = 0; r < 4; r++) s[ni][r] = 0.f;
#pragma unroll
        for (int ks = 0; ks < 64; ks += 8) {
            uint32_t a[4];
            a[0] = __float_as_uint(Qs[(rm + group)     * QS_ST + ks + tig]);
            a[1] = __float_as_uint(Qs[(rm + group + 8) * QS_ST + ks + tig]);
            a[2] = __float_as_uint(Qs[(rm + group)     * QS_ST + ks + tig + 4]);
            a[3] = __float_as_uint(Qs[(rm + group + 8) * QS_ST + ks + tig + 4]);
#pragma unroll
            for (int ni = 0; ni < 8; ni++) {
                uint32_t bb[2];
                bb[0] = __float_as_uint(KT[(ks + tig)     * KT_ST + ni * 8 + group]);
                bb[1] = __float_as_uint(KT[(ks + tig + 4) * KT_ST + ni * 8 + group]);
                mma_tf32(s[ni], a, bb);
            }
        }
        int row0 = qt0 + rm + group;
        bool diag = (jt == jt_max);
#pragma unroll
        for (int ni = 0; ni < 8; ni++) {
#pragma unroll
            for (int r = 0; r < 4; r++) s[ni][r] *= 0.125f;
            if (diag) {
                int c0 = j0 + ni * 8 + 2 * tig;
                if (c0     > row0)     s[ni][0] = -1e30f;
                if (c0 + 1 > row0)     s[ni][1] = -1e30f;
                if (c0     > row0 + 8) s[ni][2] = -1e30f;
                if (c0 + 1 > row0 + 8) s[ni][3] = -1e30f;
            }
        }
        // ---- online softmax ----
        float tm0 = -1e30f, tm1 = -1e30f;
#pragma unroll
        for (int ni = 0; ni < 8; ni++) {
            tm0 = fmaxf(tm0, fmaxf(s[ni][0], s[ni][1]));
            tm1 = fmaxf(tm1, fmaxf(s[ni][2], s[ni][3]));
        }
        tm0 = fmaxf(tm0, __shfl_xor_sync(0xffffffffu, tm0, 1));
        tm0 = fmaxf(tm0, __shfl_xor_sync(0xffffffffu, tm0, 2));
        tm1 = fmaxf(tm1, __shfl_xor_sync(0xffffffffu, tm1, 1));
        tm1 = fmaxf(tm1, __shfl_xor_sync(0xffffffffu, tm1, 2));
        float nm0 = fmaxf(m0, tm0), nm1 = fmaxf(m1, tm1);
        float f0 = __expf(m0 - nm0), f1 = __expf(m1 - nm1);
        float rs0 = 0.f, rs1 = 0.f;
#pragma unroll
        for (int ni = 0; ni < 8; ni++) {
            s[ni][0] = __expf(s[ni][0] - nm0);
            s[ni][1] = __expf(s[ni][1] - nm0);
            s[ni][2] = __expf(s[ni][2] - nm1);
            s[ni][3] = __expf(s[ni][3] - nm1);
            rs0 += s[ni][0] + s[ni][1];
            rs1 += s[ni][2] + s[ni][3];
        }
        rs0 += __shfl_xor_sync(0xffffffffu, rs0, 1);
        rs0 += __shfl_xor_sync(0xffffffffu, rs0, 2);
        rs1 += __shfl_xor_sync(0xffffffffu, rs1, 1);
        rs1 += __shfl_xor_sync(0xffffffffu, rs1, 2);
        l0 = l0 * f0 + rs0; l1 = l1 * f1 + rs1;
        m0 = nm0; m1 = nm1;
#pragma unroll
        for (int ni = 0; ni < 8; ni++) {
            o[ni][0] *= f0; o[ni][1] *= f0; o[ni][2] *= f1; o[ni][3] *= f1;
        }
        // ---- P -> warp-private smem, then O += P V ----
#pragma unroll
        for (int ni = 0; ni < 8; ni++) {
            int c = ni * 8 + 2 * tig;
            Ps[(rm + group)     * PS_ST + c    ] = tf32r(s[ni][0]);
            Ps[(rm + group)     * PS_ST + c + 1] = tf32r(s[ni][1]);
            Ps[(rm + group + 8) * PS_ST + c    ] = tf32r(s[ni][2]);
            Ps[(rm + group + 8) * PS_ST + c + 1] = tf32r(s[ni][3]);
        }
        __syncwarp();
#pragma unroll
        for (int ks = 0; ks < 64; ks += 8) {
            uint32_t a[4];
            a[0] = __float_as_uint(Ps[(rm + group)     * PS_ST + ks + tig]);
            a[1] = __float_as_uint(Ps[(rm + group + 8) * PS_ST + ks + tig]);
            a[2] = __float_as_uint(Ps[(rm + group)     * PS_ST + ks + tig + 4]);
            a[3] = __float_as_uint(Ps[(rm + group + 8) * PS_ST + ks + tig + 4]);
#pragma unroll
            for (int ni = 0; ni < 8; ni++) {
                uint32_t bb[2];
                bb[0] = __float_as_uint(Vs[(ks + tig)     * VS_ST + ni * 8 + group]);
                bb[1] = __float_as_uint(Vs[(ks + tig + 4) * VS_ST + ni * 8 + group]);
                mma_tf32(o[ni], a, bb);
            }
        }
        __syncwarp();
    }

    float inv0 = 1.f / l0, inv1 = 1.f / l1;
    int r0 = qt0 + rm + group;
#pragma unroll
    for (int ni = 0; ni < 8; ni++) {
        int c = ni * 8 + 2 * tig;
        float2 w0 = make_float2(o[ni][0] * inv0, o[ni][1] * inv0);
        float2 w1 = make_float2(o[ni][2] * inv1, o[ni][3] * inv1);
        *(float2*)&out[(size_t)(b * SEQ + r0)     * DMODEL + h * 64 + c] = w0;
        *(float2*)&out[(size_t)(b * SEQ + r0 + 8) * DMODEL + h * 64 + c] = w1;
    }
}

// ---------------- swiglu elementwise (float4) --------------------------------
__global__ void swiglu_kernel(float4* __restrict__ u, const float4* __restrict__ v, int n4) {
    int i = blockIdx.x * blockDim.x + threadIdx.x;
    if (i < n4) {
        float4 a = u[i], b = v[i];
        a.x = a.x / (1.f + expf(-a.x)) * b.x;
        a.y = a.y / (1.f + expf(-a.y)) * b.y;
        a.z = a.z / (1.f + expf(-a.z)) * b.z;
        a.w = a.w / (1.f + expf(-a.w)) * b.w;
        u[i] = a;
    }
}

// ---------------- halt head --------------------------------------------------
__global__ void halt_kernel(const float* __restrict__ hh, const float* __restrict__ Wh2,
                            const float* __restrict__ bh2, const float* __restrict__ cum,
                            float* __restrict__ halt_out, float* __restrict__ cum_out) {
    int row = blockIdx.x;
    int t = threadIdx.x;
    float p = hh[(size_t)row * DHALT + t] * Wh2[t];
    for (int off = 16; off; off >>= 1) p += __shfl_xor_sync(0xffffffffu, p, off);
    __shared__ float red[8];
    if ((t & 31) == 0) red[t >> 5] = p;
    __syncthreads();
    if (t == 0) {
        float sum = red[0] + red[1] + red[2] + red[3] + red[4] + red[5] + red[6] + red[7] + bh2[0];
        float hp = 1.f / (1.f + expf(-sum));
        float c = cum[row];
        float still = (c < 0.99f) ? 1.f : 0.f;
        halt_out[row] = hp;
        cum_out[row] = c + hp * still;
    }
}

// ---------------- launch ------------------------------------------------------
extern "C" void kernel_launch(void* const* d_in, const int* in_sizes, int n_in,
                              void* d_out, int out_size) {
    const float* x    = (const float*)d_in[0];
    const float* cum  = (const float*)d_in[1];
    const float* g1   = (const float*)d_in[2];
    const float* g2   = (const float*)d_in[3];
    const float* Wqkv = (const float*)d_in[4];
    const float* Wo   = (const float*)d_in[5];
    const float* W1   = (const float*)d_in[6];
    const float* W2   = (const float*)d_in[7];
    const float* W3   = (const float*)d_in[8];
    const float* Wh1  = (const float*)d_in[9];
    const float* bh1  = (const float*)d_in[10];
    const float* Wh2  = (const float*)d_in[11];
    const float* bh2  = (const float*)d_in[12];

    float* outx = (float*)d_out;
    float* outh = outx + (size_t)NROWS * DMODEL;
    float* outc = outh + NROWS;

    float *h1, *qkvb, *attnb, *x1, *h2, *u, *v, *hhp;
    cudaGetSymbolAddress((void**)&h1,   g_h1);
    cudaGetSymbolAddress((void**)&qkvb, g_qkv);
    cudaGetSymbolAddress((void**)&attnb,g_attn);
    cudaGetSymbolAddress((void**)&x1,   g_x1);
    cudaGetSymbolAddress((void**)&h2,   g_h2);
    cudaGetSymbolAddress((void**)&u,    g_u);
    cudaGetSymbolAddress((void**)&v,    g_v);
    cudaGetSymbolAddress((void**)&hhp,  g_hh);

    cudaFuncSetAttribute(gemm_tc<0,1,1>, cudaFuncAttributeMaxDynamicSharedMemorySize, GEMM_SMEM);
    cudaFuncSetAttribute(gemm_tc<1,1,1>, cudaFuncAttributeMaxDynamicSharedMemorySize, GEMM_SMEM);
    cudaFuncSetAttribute(gemm_tc<0,1,0>, cudaFuncAttributeMaxDynamicSharedMemorySize, GEMM_SMEM);
    cudaFuncSetAttribute(gemm_tc<1,0,1>, cudaFuncAttributeMaxDynamicSharedMemorySize, GEMM_SMEM);
    cudaFuncSetAttribute(gemm_tc<2,1,1>, cudaFuncAttributeMaxDynamicSharedMemorySize, GEMM_SMEM);
    cudaFuncSetAttribute(attn_tc, cudaFuncAttributeMaxDynamicSharedMemorySize, ATTN_SMEM);

    // 1. h1 = rmsnorm(x, g1)
    rmsnorm_kernel<<<NROWS, 256>>>(x, g1, h1);
    // 2. qkv = h1 @ Wqkv
    gemm_tc<0,1,1><<<dim3(3 * DMODEL / 128, NROWS / 128), 256, GEMM_SMEM>>>(
        h1, Wqkv, qkvb, nullptr, NROWS, DMODEL, 3 * DMODEL);
    // 3. attention (tf32 tensor cores + register-staged KV prefetch)
    attn_tc<<<dim3(SEQ / 64, BATCH * NHEAD), 128, ATTN_SMEM>>>(qkvb, attnb);
    // 4. x1 = x + attn @ Wo
    gemm_tc<1,1,1><<<dim3(DMODEL / 128, NROWS / 128), 256, GEMM_SMEM>>>(
        attnb, Wo, x1, x, NROWS, DMODEL, DMODEL);
    // 5. h2 = rmsnorm(x1, g2)
    rmsnorm_kernel<<<NROWS, 256>>>(x1, g2, h2);
    // 6. u = h2 @ W1, v = h2 @ W2
    gemm_tc<0,1,0><<<dim3((DFF + 127) / 128, NROWS / 128), 256, GEMM_SMEM>>>(
        h2, W1, u, nullptr, NROWS, DMODEL, DFF);
    gemm_tc<0,1,0><<<dim3((DFF + 127) / 128, NROWS / 128), 256, GEMM_SMEM>>>(
        h2, W2, v, nullptr, NROWS, DMODEL, DFF);
    // 7. u = silu(u) * v
    {
        int n4 = NROWS * DFF / 4;
        swiglu_kernel<<<(n4 + 255) / 256, 256>>>((float4*)u, (const float4*)v, n4);
    }
    // 8. final x = x1 + u @ W3 -> d_out
    gemm_tc<1,0,1><<<dim3(DMODEL / 128, NROWS / 128), 256, GEMM_SMEM>>>(
        u, W3, outx, x1, NROWS, DFF, DMODEL);
    // 9. hh = gelu(x @ Wh1 + bh1)
    gemm_tc<2,1,1><<<dim3(DHALT / 128, NROWS / 128), 256, GEMM_SMEM>>>(
        outx, Wh1, hhp, bh1, NROWS, DMODEL, DHALT);
    // 10. halt probs + cum update
    halt_kernel<<<NROWS, 256>>>(hhp, Wh2, bh2, cum, outh, outc);
}